// round 1
// baseline (speedup 1.0000x reference)
#include <cuda_runtime.h>
#include <math.h>

#define N_NODES 10000
#define N_EDGES 160000
#define N_TRIP  1200000
#define D_      256
#define DM_     64
#define H_      1024
#define L_      3

// ---------------- scratch (device globals; no allocation) ----------------
__device__ float    g_x[2][N_NODES * D_];          // ping-pong node features
__device__ float    g_rn[N_EDGES * 3];             // -r / |r|
__device__ float    g_bl[N_EDGES];                 // |r|
__device__ float    g_ye[(size_t)N_EDGES * 192];   // y @ Wedge[l] + bedge[l], all 3 layers
__device__ float    g_xnode[N_NODES * 128];        // [xj | xi] per node
__device__ float    g_xij[(size_t)N_EDGES * DM_];
__device__ float    g_logit[N_TRIP];
__device__ float    g_ex[N_TRIP];
__device__ unsigned g_mkey[N_EDGES];               // orderable-uint encoded segment max
__device__ float    g_den[N_EDGES];
__device__ float    g_ft[N_NODES * DM_];

// ---------------- small helpers ----------------
__device__ __forceinline__ float silu_f(float v) {
    return v * (1.0f / (1.0f + __expf(-v)));
}

// ---------------- kernels ----------------
__global__ void k_embed(const int* __restrict__ an, const float* __restrict__ emb) {
    int idx = blockIdx.x * 256 + threadIdx.x;
    if (idx >= N_NODES * D_) return;
    int n = idx >> 8, d = idx & 255;
    g_x[0][idx] = emb[an[n] * D_ + d];
}

__global__ void k_geom(const float* __restrict__ r) {
    int e = blockIdx.x * 256 + threadIdx.x;
    if (e >= N_EDGES) return;
    float x = r[e * 3], y = r[e * 3 + 1], z = r[e * 3 + 2];
    float bl = sqrtf(x * x + y * y + z * z);
    g_bl[e] = bl;
    float inv = -1.0f / bl;
    g_rn[e * 3] = x * inv; g_rn[e * 3 + 1] = y * inv; g_rn[e * 3 + 2] = z * inv;
}

// ye[e, l*64+k] = sum_d exp(-gamma*(bl_e - c_d)^2) * Wedge[l][d][k] + bedge[l][k]
// block: 192 threads (one per output column l*64+k), 32 edges per block
__global__ void k_ye(const float* __restrict__ We, const float* __restrict__ be) {
    __shared__ float ys[D_ * 32];   // [d][j]  32KB
    __shared__ float bls[32];
    int e0 = blockIdx.x * 32;
    int tid = threadIdx.x;          // 0..191
    if (tid < 32) bls[tid] = g_bl[e0 + tid];
    __syncthreads();
    for (int idx = tid; idx < 32 * D_; idx += 192) {
        int j = idx >> 8, d = idx & 255;
        float diff = bls[j] - (float)d * (8.0f / 255.0f);
        ys[d * 32 + j] = __expf(-1016.015625f * diff * diff);
    }
    __syncthreads();
    int l = tid / 64, kk = tid & 63;
    const float* W = We + l * (D_ * DM_) + kk;
    float acc[32];
#pragma unroll
    for (int j = 0; j < 32; j++) acc[j] = 0.0f;
    for (int d = 0; d < D_; d++) {
        float w = __ldg(W + d * DM_);
        const float4* yv = (const float4*)(ys + d * 32);
#pragma unroll
        for (int q = 0; q < 8; q++) {
            float4 v = yv[q];
            acc[4 * q]     += v.x * w; acc[4 * q + 1] += v.y * w;
            acc[4 * q + 2] += v.z * w; acc[4 * q + 3] += v.w * w;
        }
    }
    float b = __ldg(be + l * DM_ + kk);
#pragma unroll
    for (int j = 0; j < 32; j++)
        g_ye[(size_t)(e0 + j) * 192 + tid] = acc[j] + b;
}

// xnode[n][0:64] = x@Wsrc+bsrc ; xnode[n][64:128] = x@Wdst+bdst
// block: 128 threads, 16 nodes per block
__global__ void k_nodeproj(int cur, const float* __restrict__ Ws, const float* __restrict__ bs,
                           const float* __restrict__ Wd, const float* __restrict__ bd) {
    __shared__ float xs[D_ * 16];   // [d][j]  16KB
    int n0 = blockIdx.x * 16, tid = threadIdx.x;
    const float* x = g_x[cur];
    for (int idx = tid; idx < 16 * D_; idx += 128) {
        int j = idx >> 8, d = idx & 255;
        xs[d * 16 + j] = x[(n0 + j) * D_ + d];
    }
    __syncthreads();
    const float* W = (tid < 64) ? Ws : Wd;
    int kk = tid & 63;
    float b = ((tid < 64) ? bs : bd)[kk];
    float acc[16];
#pragma unroll
    for (int j = 0; j < 16; j++) acc[j] = 0.0f;
    for (int d = 0; d < D_; d++) {
        float w = __ldg(W + d * DM_ + kk);
        const float4* xv = (const float4*)(xs + d * 16);
#pragma unroll
        for (int q = 0; q < 4; q++) {
            float4 v = xv[q];
            acc[4 * q]     += v.x * w; acc[4 * q + 1] += v.y * w;
            acc[4 * q + 2] += v.z * w; acc[4 * q + 3] += v.w * w;
        }
    }
#pragma unroll
    for (int j = 0; j < 16; j++)
        g_xnode[(n0 + j) * 128 + tid] = acc[j] + b;
}

__global__ void k_xij(const int* __restrict__ gs, const int* __restrict__ gd, int l) {
    int idx = blockIdx.x * 256 + threadIdx.x;
    if (idx >= N_EDGES * DM_) return;
    int e = idx >> 6, k = idx & 63;
    g_xij[idx] = g_xnode[gs[e] * 128 + k] + g_xnode[gd[e] * 128 + 64 + k]
               + g_ye[(size_t)e * 192 + l * 64 + k];
}

__global__ void k_init() {
    int idx = blockIdx.x * 256 + threadIdx.x;
    if (idx < N_EDGES) { g_mkey[idx] = 0u; g_den[idx] = 0.0f; }
    if (idx < N_NODES * DM_) g_ft[idx] = 0.0f;
}

// warp per triplet: logit + segment max
__global__ void k_pass1(const int* __restrict__ t_src, const int* __restrict__ t_dst,
                        const float* __restrict__ attn_l) {
    int t = blockIdx.x * 8 + (threadIdx.x >> 5);
    if (t >= N_TRIP) return;
    int lane = threadIdx.x & 31;
    int ts = __ldg(t_src + t), td = __ldg(t_dst + t);
    float ax = g_rn[ts * 3], ay = g_rn[ts * 3 + 1], az = g_rn[ts * 3 + 2];
    float bx = g_rn[td * 3], by = g_rn[td * 3 + 1], bz = g_rn[td * 3 + 2];
    float c = ax * bx + ay * by + az * bz;
    c = fminf(1.0f, fmaxf(-1.0f, c));
    float s = sqrtf(fmaxf(0.0f, 1.0f - c * c));
    // Chebyshev T_k(c) = Re((c+is)^k) via binary exponentiation.
    float r2 = c * c - s * s,    i2 = 2.0f * c * s;
    float r4 = r2 * r2 - i2 * i2, i4 = 2.0f * r2 * i2;
    float r8 = r4 * r4 - i4 * i4, i8 = 2.0f * r4 * i4;
    float r16 = r8 * r8 - i8 * i8, i16 = 2.0f * r8 * i8;
    float r32 = r16 * r16 - i16 * i16, i32 = 2.0f * r16 * i16;
    // u = w^(2*lane): bits 0..4 of lane select w^2,w^4,w^8,w^16,w^32
    float ur = (lane & 1) ? r2 : 1.0f;
    float ui = (lane & 1) ? i2 : 0.0f;
    {
        float qr = (lane & 2) ? r4 : 1.0f, qi = (lane & 2) ? i4 : 0.0f;
        float tr = ur * qr - ui * qi; ui = ur * qi + ui * qr; ur = tr;
    }
    {
        float qr = (lane & 4) ? r8 : 1.0f, qi = (lane & 4) ? i8 : 0.0f;
        float tr = ur * qr - ui * qi; ui = ur * qi + ui * qr; ur = tr;
    }
    {
        float qr = (lane & 8) ? r16 : 1.0f, qi = (lane & 8) ? i16 : 0.0f;
        float tr = ur * qr - ui * qi; ui = ur * qi + ui * qr; ur = tr;
    }
    {
        float qr = (lane & 16) ? r32 : 1.0f, qi = (lane & 16) ? i32 : 0.0f;
        float tr = ur * qr - ui * qi; ui = ur * qi + ui * qr; ur = tr;
    }
    float z0 = ur;                       // cos(2*lane * theta)
    float z1 = ur * c - ui * s;          // cos((2*lane+1) * theta)
    float2 xsv = *(const float2*)&g_xij[(size_t)ts * DM_ + 2 * lane];
    float2 xdv = *(const float2*)&g_xij[(size_t)td * DM_ + 2 * lane];
    float e0 = silu_f(z0 + xsv.x + xdv.x);
    float e1 = silu_f(z1 + xsv.y + xdv.y);
    float p = e0 * __ldg(attn_l + 2 * lane) + e1 * __ldg(attn_l + 2 * lane + 1);
#pragma unroll
    for (int off = 16; off; off >>= 1) p += __shfl_xor_sync(0xffffffffu, p, off);
    if (lane == 0) {
        g_logit[t] = p;
        unsigned u = __float_as_uint(p);
        unsigned key = (u & 0x80000000u) ? ~u : (u | 0x80000000u);
        atomicMax(&g_mkey[td], key);
    }
}

__global__ void k_pass2(const int* __restrict__ t_dst) {
    int t = blockIdx.x * 256 + threadIdx.x;
    if (t >= N_TRIP) return;
    int td = __ldg(t_dst + t);
    unsigned k = g_mkey[td];
    float m = (k & 0x80000000u) ? __uint_as_float(k ^ 0x80000000u) : __uint_as_float(~k);
    float exv = __expf(g_logit[t] - m);
    g_ex[t] = exv;
    atomicAdd(&g_den[td], exv);
}

// warp per triplet: ft[node] += a * xij[t_src]
__global__ void k_pass3(const int* __restrict__ t_src, const int* __restrict__ t_dst,
                        const int* __restrict__ gdst) {
    int t = blockIdx.x * 8 + (threadIdx.x >> 5);
    if (t >= N_TRIP) return;
    int lane = threadIdx.x & 31;
    int ts = __ldg(t_src + t), td = __ldg(t_dst + t);
    float a = g_ex[t] / g_den[td];
    int node = __ldg(gdst + td);
    float2 xv = *(const float2*)&g_xij[(size_t)ts * DM_ + 2 * lane];
    atomicAdd(&g_ft[node * DM_ + 2 * lane],     a * xv.x);
    atomicAdd(&g_ft[node * DM_ + 2 * lane + 1], a * xv.y);
}

// fused FFN: x_out = silu(ft @ W1 + b1) @ W2 + b2   (64 -> 1024 -> 256)
// block: 256 threads (one per output col), 16 nodes per block, hidden in two 512-chunks
__global__ void k_ffn(int nxt, const float* __restrict__ W1, const float* __restrict__ b1,
                      const float* __restrict__ W2, const float* __restrict__ b2) {
    __shared__ float fts[DM_ * 16];   // [d][j]   4KB
    __shared__ float hs[512 * 16];    // [hl][j] 32KB
    int n0 = blockIdx.x * 16, tid = threadIdx.x;
    for (int idx = tid; idx < 16 * DM_; idx += 256) {
        int j = idx >> 6, d = idx & 63;
        fts[d * 16 + j] = g_ft[(n0 + j) * DM_ + d];
    }
    float acc2[16];
#pragma unroll
    for (int j = 0; j < 16; j++) acc2[j] = 0.0f;
    for (int ch = 0; ch < 2; ch++) {
        __syncthreads();
#pragma unroll
        for (int rep = 0; rep < 2; rep++) {
            int hl = rep * 256 + tid;
            int hh = ch * 512 + hl;
            float acc[16];
#pragma unroll
            for (int j = 0; j < 16; j++) acc[j] = 0.0f;
            for (int d = 0; d < DM_; d++) {
                float w = __ldg(W1 + d * H_ + hh);
                const float4* fv = (const float4*)(fts + d * 16);
#pragma unroll
                for (int q = 0; q < 4; q++) {
                    float4 v = fv[q];
                    acc[4 * q]     += v.x * w; acc[4 * q + 1] += v.y * w;
                    acc[4 * q + 2] += v.z * w; acc[4 * q + 3] += v.w * w;
                }
            }
            float bb = __ldg(b1 + hh);
            float4* hv = (float4*)(hs + hl * 16);
#pragma unroll
            for (int q = 0; q < 4; q++) {
                float4 o;
                o.x = silu_f(acc[4 * q] + bb);
                o.y = silu_f(acc[4 * q + 1] + bb);
                o.z = silu_f(acc[4 * q + 2] + bb);
                o.w = silu_f(acc[4 * q + 3] + bb);
                hv[q] = o;
            }
        }
        __syncthreads();
        for (int hl = 0; hl < 512; hl++) {
            float w = __ldg(W2 + (ch * 512 + hl) * D_ + tid);
            const float4* hv = (const float4*)(hs + hl * 16);
#pragma unroll
            for (int q = 0; q < 4; q++) {
                float4 v = hv[q];
                acc2[4 * q]     += v.x * w; acc2[4 * q + 1] += v.y * w;
                acc2[4 * q + 2] += v.z * w; acc2[4 * q + 3] += v.w * w;
            }
        }
    }
    float bb = __ldg(b2 + tid);
    float* xo = g_x[nxt];
#pragma unroll
    for (int j = 0; j < 16; j++)
        xo[(n0 + j) * D_ + tid] = acc2[j] + bb;
}

__global__ void k_zero(float* out) {
    if (blockIdx.x == 0 && threadIdx.x == 0) out[0] = 0.0f;
}

__global__ void k_fc(int cur, const float* __restrict__ Wfc, const float* __restrict__ bfc,
                     float* out) {
    __shared__ float wf[D_];
    __shared__ float red[8];
    for (int i = threadIdx.x; i < D_; i += 256) wf[i] = Wfc[i];
    __syncthreads();
    const float* x = g_x[cur];
    float local = 0.0f;
    int stride = gridDim.x * 256;
    for (int idx = blockIdx.x * 256 + threadIdx.x; idx < N_NODES * D_; idx += stride)
        local += x[idx] * wf[idx & 255];
#pragma unroll
    for (int off = 16; off; off >>= 1) local += __shfl_xor_sync(0xffffffffu, local, off);
    if ((threadIdx.x & 31) == 0) red[threadIdx.x >> 5] = local;
    __syncthreads();
    if (threadIdx.x < 8) {
        float v = red[threadIdx.x];
#pragma unroll
        for (int off = 4; off; off >>= 1) v += __shfl_xor_sync(0xffu, v, off);
        if (threadIdx.x == 0) atomicAdd(out, v * (1.0f / (float)N_NODES));
    }
    if (blockIdx.x == 0 && threadIdx.x == 0) atomicAdd(out, __ldg(bfc));
}

// ---------------- host ----------------
extern "C" void kernel_launch(void* const* d_in, const int* in_sizes, int n_in,
                              void* d_out, int out_size) {
    const int*   an    = (const int*)d_in[0];
    const int*   gs    = (const int*)d_in[1];
    const int*   gd    = (const int*)d_in[2];
    const int*   tsp   = (const int*)d_in[3];
    const int*   tdp   = (const int*)d_in[4];
    const float* r     = (const float*)d_in[5];
    const float* emb   = (const float*)d_in[6];
    const float* Wsrc  = (const float*)d_in[7];
    const float* bsrc  = (const float*)d_in[8];
    const float* Wdst  = (const float*)d_in[9];
    const float* bdst  = (const float*)d_in[10];
    const float* Wedge = (const float*)d_in[11];
    const float* bedge = (const float*)d_in[12];
    const float* attn  = (const float*)d_in[13];
    const float* W1    = (const float*)d_in[14];
    const float* b1    = (const float*)d_in[15];
    const float* W2    = (const float*)d_in[16];
    const float* b2    = (const float*)d_in[17];
    const float* Wfc   = (const float*)d_in[18];
    const float* bfc   = (const float*)d_in[19];
    float* out = (float*)d_out;

    k_embed<<<(N_NODES * D_ + 255) / 256, 256>>>(an, emb);
    k_geom<<<(N_EDGES + 255) / 256, 256>>>(r);
    k_ye<<<N_EDGES / 32, 192>>>(Wedge, bedge);

    int cur = 0;
    for (int l = 0; l < L_; l++) {
        k_nodeproj<<<N_NODES / 16, 128>>>(cur, Wsrc + l * D_ * DM_, bsrc + l * DM_,
                                          Wdst + l * D_ * DM_, bdst + l * DM_);
        k_xij<<<(N_EDGES * DM_ + 255) / 256, 256>>>(gs, gd, l);
        k_init<<<(N_NODES * DM_ + 255) / 256, 256>>>();
        k_pass1<<<N_TRIP / 8, 256>>>(tsp, tdp, attn + l * DM_);
        k_pass2<<<(N_TRIP + 255) / 256, 256>>>(tdp);
        k_pass3<<<N_TRIP / 8, 256>>>(tsp, tdp, gd);
        k_ffn<<<N_NODES / 16, 256>>>(1 - cur, W1 + l * DM_ * H_, b1 + l * H_,
                                     W2 + l * H_ * D_, b2 + l * D_);
        cur = 1 - cur;
    }
    k_zero<<<1, 1>>>(out);
    k_fc<<<256, 256>>>(cur, Wfc, bfc, out);
}

// round 2
// speedup vs baseline: 1.1074x; 1.1074x over previous
#include <cuda_runtime.h>
#include <math.h>

#define N_NODES 10000
#define N_EDGES 160000
#define N_TRIP  1200000
#define D_      256
#define DM_     64
#define H_      1024
#define L_      3

typedef unsigned long long ull;

// ---------------- scratch (device globals; no allocation) ----------------
__device__ float g_x[2][N_NODES * D_];          // ping-pong node features
__device__ float g_rn[N_EDGES * 3];             // -r / |r|
__device__ float g_bl[N_EDGES];                 // |r|
__device__ float g_ye[(size_t)N_EDGES * 192];   // y @ Wedge[l] + bedge[l], all 3 layers
__device__ float g_xnode[N_NODES * 128];        // [xj | xi] per node
__device__ float g_xij[(size_t)N_EDGES * DM_];
__device__ float g_ex[N_TRIP];
__device__ float g_den[N_EDGES];
__device__ float g_ft[N_NODES * DM_];

// ---------------- helpers ----------------
__device__ __forceinline__ float silu_f(float v) {
    return v * (1.0f / (1.0f + __expf(-v)));
}
__device__ __forceinline__ ull pk2(float x, float y) {
    ull r; asm("mov.b64 %0, {%1, %2};" : "=l"(r) : "f"(x), "f"(y)); return r;
}
__device__ __forceinline__ float2 up2(ull v) {
    float2 r; asm("mov.b64 {%0, %1}, %2;" : "=f"(r.x), "=f"(r.y) : "l"(v)); return r;
}
__device__ __forceinline__ void fma2(ull& d, ull a, ull b) {
    asm("fma.rn.f32x2 %0, %1, %2, %0;" : "+l"(d) : "l"(a), "l"(b));
}

// ---------------- kernels ----------------
__global__ void k_embed(const int* __restrict__ an, const float* __restrict__ emb) {
    int idx = blockIdx.x * 256 + threadIdx.x;
    if (idx >= N_NODES * D_) return;
    int n = idx >> 8, d = idx & 255;
    g_x[0][idx] = emb[an[n] * D_ + d];
}

__global__ void k_geom(const float* __restrict__ r) {
    int e = blockIdx.x * 256 + threadIdx.x;
    if (e >= N_EDGES) return;
    float x = r[e * 3], y = r[e * 3 + 1], z = r[e * 3 + 2];
    float bl = sqrtf(x * x + y * y + z * z);
    g_bl[e] = bl;
    float inv = -1.0f / bl;
    g_rn[e * 3] = x * inv; g_rn[e * 3 + 1] = y * inv; g_rn[e * 3 + 2] = z * inv;
}

// ye[e, l*64+k] = RBF(bl_e) . Wedge[l][:,k] + bedge[l][k]
// block: 192 threads (one per output column l*64+k), 32 edges per block
__global__ void k_ye(const float* __restrict__ We, const float* __restrict__ be) {
    __shared__ float ys[D_ * 32];   // [d][j]  32KB
    __shared__ float bls[32];
    int e0 = blockIdx.x * 32;
    int tid = threadIdx.x;          // 0..191
    if (tid < 32) bls[tid] = g_bl[e0 + tid];
    __syncthreads();
    for (int idx = tid; idx < 32 * D_; idx += 192) {
        int j = idx >> 8, d = idx & 255;
        float diff = bls[j] - (float)d * (8.0f / 255.0f);
        ys[d * 32 + j] = __expf(-1016.015625f * diff * diff);
    }
    __syncthreads();
    int l = tid / 64, kk = tid & 63;
    const float* W = We + l * (D_ * DM_) + kk;
    ull acc[16];
#pragma unroll
    for (int q = 0; q < 16; q++) acc[q] = 0ull;
    for (int d = 0; d < D_; d++) {
        float w = __ldg(W + d * DM_);
        ull wz = pk2(w, w);
        const ulonglong2* yv = (const ulonglong2*)(ys + d * 32);
#pragma unroll
        for (int q = 0; q < 8; q++) {
            ulonglong2 v = yv[q];
            fma2(acc[2 * q], v.x, wz);
            fma2(acc[2 * q + 1], v.y, wz);
        }
    }
    float b = __ldg(be + l * DM_ + kk);
#pragma unroll
    for (int q = 0; q < 16; q++) {
        float2 v = up2(acc[q]);
        g_ye[(size_t)(e0 + 2 * q) * 192 + tid]     = v.x + b;
        g_ye[(size_t)(e0 + 2 * q + 1) * 192 + tid] = v.y + b;
    }
}

// xnode[n][0:64] = x@Wsrc+bsrc ; xnode[n][64:128] = x@Wdst+bdst
// block: 128 threads, 8 nodes per block (1250 blocks for occupancy)
__global__ void k_nodeproj(int cur, const float* __restrict__ Ws, const float* __restrict__ bs,
                           const float* __restrict__ Wd, const float* __restrict__ bd) {
    __shared__ float xs[D_ * 8];   // [d][j]  8KB
    int n0 = blockIdx.x * 8, tid = threadIdx.x;
    const float* x = g_x[cur];
    for (int idx = tid; idx < 8 * D_; idx += 128) {
        int j = idx >> 8, d = idx & 255;
        xs[d * 8 + j] = x[(n0 + j) * D_ + d];
    }
    __syncthreads();
    const float* W = (tid < 64) ? Ws : Wd;
    int kk = tid & 63;
    float b = ((tid < 64) ? bs : bd)[kk];
    ull acc[4];
#pragma unroll
    for (int q = 0; q < 4; q++) acc[q] = 0ull;
    for (int d = 0; d < D_; d++) {
        float w = __ldg(W + d * DM_ + kk);
        ull wz = pk2(w, w);
        const ulonglong2* xv = (const ulonglong2*)(xs + d * 8);
#pragma unroll
        for (int q = 0; q < 2; q++) {
            ulonglong2 v = xv[q];
            fma2(acc[2 * q], v.x, wz);
            fma2(acc[2 * q + 1], v.y, wz);
        }
    }
#pragma unroll
    for (int q = 0; q < 4; q++) {
        float2 v = up2(acc[q]);
        g_xnode[(n0 + 2 * q) * 128 + tid]     = v.x + b;
        g_xnode[(n0 + 2 * q + 1) * 128 + tid] = v.y + b;
    }
}

__global__ void k_xij(const int* __restrict__ gs, const int* __restrict__ gd, int l) {
    int idx = blockIdx.x * 256 + threadIdx.x;
    if (idx >= N_EDGES * DM_) return;
    int e = idx >> 6, k = idx & 63;
    g_xij[idx] = g_xnode[gs[e] * 128 + k] + g_xnode[gd[e] * 128 + 64 + k]
               + g_ye[(size_t)e * 192 + l * 64 + k];
}

__global__ void k_init() {
    int idx = blockIdx.x * 256 + threadIdx.x;
    if (idx < N_EDGES) g_den[idx] = 0.0f;
    if (idx < N_NODES * DM_) g_ft[idx] = 0.0f;
}

// warp per triplet: logit -> exp -> atomic denominator (max-shift elided; logits bounded)
__global__ void k_pass1(const int* __restrict__ t_src, const int* __restrict__ t_dst,
                        const float* __restrict__ attn_l) {
    int t = blockIdx.x * 8 + (threadIdx.x >> 5);
    if (t >= N_TRIP) return;
    int lane = threadIdx.x & 31;
    int ts = __ldg(t_src + t), td = __ldg(t_dst + t);
    float ax = g_rn[ts * 3], ay = g_rn[ts * 3 + 1], az = g_rn[ts * 3 + 2];
    float bx = g_rn[td * 3], by = g_rn[td * 3 + 1], bz = g_rn[td * 3 + 2];
    float c = ax * bx + ay * by + az * bz;
    c = fminf(1.0f, fmaxf(-1.0f, c));
    float s = sqrtf(fmaxf(0.0f, 1.0f - c * c));
    // Chebyshev T_k(c) = Re((c+is)^k) via binary exponentiation.
    float r2 = c * c - s * s,    i2 = 2.0f * c * s;
    float r4 = r2 * r2 - i2 * i2, i4 = 2.0f * r2 * i2;
    float r8 = r4 * r4 - i4 * i4, i8 = 2.0f * r4 * i4;
    float r16 = r8 * r8 - i8 * i8, i16 = 2.0f * r8 * i8;
    float r32 = r16 * r16 - i16 * i16, i32 = 2.0f * r16 * i16;
    float ur = (lane & 1) ? r2 : 1.0f;
    float ui = (lane & 1) ? i2 : 0.0f;
    {
        float qr = (lane & 2) ? r4 : 1.0f, qi = (lane & 2) ? i4 : 0.0f;
        float tr = ur * qr - ui * qi; ui = ur * qi + ui * qr; ur = tr;
    }
    {
        float qr = (lane & 4) ? r8 : 1.0f, qi = (lane & 4) ? i8 : 0.0f;
        float tr = ur * qr - ui * qi; ui = ur * qi + ui * qr; ur = tr;
    }
    {
        float qr = (lane & 8) ? r16 : 1.0f, qi = (lane & 8) ? i16 : 0.0f;
        float tr = ur * qr - ui * qi; ui = ur * qi + ui * qr; ur = tr;
    }
    {
        float qr = (lane & 16) ? r32 : 1.0f, qi = (lane & 16) ? i32 : 0.0f;
        float tr = ur * qr - ui * qi; ui = ur * qi + ui * qr; ur = tr;
    }
    float z0 = ur;                       // cos(2*lane * theta)
    float z1 = ur * c - ui * s;          // cos((2*lane+1) * theta)
    float2 xsv = *(const float2*)&g_xij[(size_t)ts * DM_ + 2 * lane];
    float2 xdv = *(const float2*)&g_xij[(size_t)td * DM_ + 2 * lane];
    float e0 = silu_f(z0 + xsv.x + xdv.x);
    float e1 = silu_f(z1 + xsv.y + xdv.y);
    float p = e0 * __ldg(attn_l + 2 * lane) + e1 * __ldg(attn_l + 2 * lane + 1);
#pragma unroll
    for (int off = 16; off; off >>= 1) p += __shfl_xor_sync(0xffffffffu, p, off);
    if (lane == 0) {
        float exv = __expf(p);
        g_ex[t] = exv;
        atomicAdd(&g_den[td], exv);
    }
}

// warp per triplet: ft[node] += a * xij[t_src]   (vector red.v2.f32)
__global__ void k_pass3(const int* __restrict__ t_src, const int* __restrict__ t_dst,
                        const int* __restrict__ gdst) {
    int t = blockIdx.x * 8 + (threadIdx.x >> 5);
    if (t >= N_TRIP) return;
    int lane = threadIdx.x & 31;
    int ts = __ldg(t_src + t), td = __ldg(t_dst + t);
    float a = g_ex[t] / g_den[td];
    int node = __ldg(gdst + td);
    float2 xv = *(const float2*)&g_xij[(size_t)ts * DM_ + 2 * lane];
    float* p = &g_ft[node * DM_ + 2 * lane];
    asm volatile("red.global.add.v2.f32 [%0], {%1, %2};"
                 :: "l"(p), "f"(a * xv.x), "f"(a * xv.y) : "memory");
}

// fused FFN: x_out = silu(ft @ W1 + b1) @ W2 + b2   (64 -> 1024 -> 256)
// block: 256 threads, 16 nodes per block; hidden kept in smem, two 512-chunks
__global__ void k_ffn(int nxt, const float* __restrict__ W1, const float* __restrict__ b1,
                      const float* __restrict__ W2, const float* __restrict__ b2) {
    __shared__ float fts[DM_ * 16];   // [d][j]   4KB
    __shared__ float hs[512 * 16];    // [hl][j] 32KB
    int n0 = blockIdx.x * 16, tid = threadIdx.x;
    for (int idx = tid; idx < 16 * DM_; idx += 256) {
        int j = idx >> 6, d = idx & 63;
        fts[d * 16 + j] = g_ft[(n0 + j) * DM_ + d];
    }
    ull acc2[8];
#pragma unroll
    for (int q = 0; q < 8; q++) acc2[q] = 0ull;
    for (int ch = 0; ch < 2; ch++) {
        __syncthreads();
#pragma unroll
        for (int rep = 0; rep < 2; rep++) {
            int hl = rep * 256 + tid;
            int hh = ch * 512 + hl;
            ull acc[8];
#pragma unroll
            for (int q = 0; q < 8; q++) acc[q] = 0ull;
            for (int d = 0; d < DM_; d++) {
                float w = __ldg(W1 + d * H_ + hh);
                ull wz = pk2(w, w);
                const ulonglong2* fv = (const ulonglong2*)(fts + d * 16);
#pragma unroll
                for (int q = 0; q < 4; q++) {
                    ulonglong2 v = fv[q];
                    fma2(acc[2 * q], v.x, wz);
                    fma2(acc[2 * q + 1], v.y, wz);
                }
            }
            float bb = __ldg(b1 + hh);
            float2* hv = (float2*)(hs + hl * 16);
#pragma unroll
            for (int q = 0; q < 8; q++) {
                float2 v = up2(acc[q]);
                hv[q] = make_float2(silu_f(v.x + bb), silu_f(v.y + bb));
            }
        }
        __syncthreads();
        for (int hl = 0; hl < 512; hl++) {
            float w = __ldg(W2 + (ch * 512 + hl) * D_ + tid);
            ull wz = pk2(w, w);
            const ulonglong2* hv = (const ulonglong2*)(hs + hl * 16);
#pragma unroll
            for (int q = 0; q < 4; q++) {
                ulonglong2 v = hv[q];
                fma2(acc2[2 * q], v.x, wz);
                fma2(acc2[2 * q + 1], v.y, wz);
            }
        }
    }
    float bb = __ldg(b2 + tid);
    float* xo = g_x[nxt];
#pragma unroll
    for (int q = 0; q < 8; q++) {
        float2 v = up2(acc2[q]);
        xo[(n0 + 2 * q) * D_ + tid]     = v.x + bb;
        xo[(n0 + 2 * q + 1) * D_ + tid] = v.y + bb;
    }
}

__global__ void k_zero(float* out) {
    if (blockIdx.x == 0 && threadIdx.x == 0) out[0] = 0.0f;
}

__global__ void k_fc(int cur, const float* __restrict__ Wfc, const float* __restrict__ bfc,
                     float* out) {
    __shared__ float wf[D_];
    __shared__ float red[8];
    for (int i = threadIdx.x; i < D_; i += 256) wf[i] = Wfc[i];
    __syncthreads();
    const float* x = g_x[cur];
    float local = 0.0f;
    int stride = gridDim.x * 256;
    for (int idx = blockIdx.x * 256 + threadIdx.x; idx < N_NODES * D_; idx += stride)
        local += x[idx] * wf[idx & 255];
#pragma unroll
    for (int off = 16; off; off >>= 1) local += __shfl_xor_sync(0xffffffffu, local, off);
    if ((threadIdx.x & 31) == 0) red[threadIdx.x >> 5] = local;
    __syncthreads();
    if (threadIdx.x < 8) {
        float v = red[threadIdx.x];
#pragma unroll
        for (int off = 4; off; off >>= 1) v += __shfl_xor_sync(0xffu, v, off);
        if (threadIdx.x == 0) atomicAdd(out, v * (1.0f / (float)N_NODES));
    }
    if (blockIdx.x == 0 && threadIdx.x == 0) atomicAdd(out, __ldg(bfc));
}

// ---------------- host ----------------
extern "C" void kernel_launch(void* const* d_in, const int* in_sizes, int n_in,
                              void* d_out, int out_size) {
    const int*   an    = (const int*)d_in[0];
    const int*   gs    = (const int*)d_in[1];
    const int*   gd    = (const int*)d_in[2];
    const int*   tsp   = (const int*)d_in[3];
    const int*   tdp   = (const int*)d_in[4];
    const float* r     = (const float*)d_in[5];
    const float* emb   = (const float*)d_in[6];
    const float* Wsrc  = (const float*)d_in[7];
    const float* bsrc  = (const float*)d_in[8];
    const float* Wdst  = (const float*)d_in[9];
    const float* bdst  = (const float*)d_in[10];
    const float* Wedge = (const float*)d_in[11];
    const float* bedge = (const float*)d_in[12];
    const float* attn  = (const float*)d_in[13];
    const float* W1    = (const float*)d_in[14];
    const float* b1    = (const float*)d_in[15];
    const float* W2    = (const float*)d_in[16];
    const float* b2    = (const float*)d_in[17];
    const float* Wfc   = (const float*)d_in[18];
    const float* bfc   = (const float*)d_in[19];
    float* out = (float*)d_out;

    k_embed<<<(N_NODES * D_ + 255) / 256, 256>>>(an, emb);
    k_geom<<<(N_EDGES + 255) / 256, 256>>>(r);
    k_ye<<<N_EDGES / 32, 192>>>(Wedge, bedge);

    int cur = 0;
    for (int l = 0; l < L_; l++) {
        k_nodeproj<<<N_NODES / 8, 128>>>(cur, Wsrc + l * D_ * DM_, bsrc + l * DM_,
                                         Wdst + l * D_ * DM_, bdst + l * DM_);
        k_xij<<<(N_EDGES * DM_ + 255) / 256, 256>>>(gs, gd, l);
        k_init<<<(N_NODES * DM_ + 255) / 256, 256>>>();
        k_pass1<<<N_TRIP / 8, 256>>>(tsp, tdp, attn + l * DM_);
        k_pass3<<<N_TRIP / 8, 256>>>(tsp, tdp, gd);
        k_ffn<<<N_NODES / 16, 256>>>(1 - cur, W1 + l * DM_ * H_, b1 + l * H_,
                                     W2 + l * H_ * D_, b2 + l * D_);
        cur = 1 - cur;
    }
    k_zero<<<1, 1>>>(out);
    k_fc<<<256, 256>>>(cur, Wfc, bfc, out);
}

// round 3
// speedup vs baseline: 1.3541x; 1.2228x over previous
#include <cuda_runtime.h>
#include <math.h>

#define N_NODES 10000
#define N_EDGES 160000
#define N_TRIP  1200000
#define D_      256
#define DM_     64
#define H_      1024
#define L_      3

typedef unsigned long long ull;

// ---------------- scratch (device globals; no allocation) ----------------
__device__ float g_x[2][N_NODES * D_];          // ping-pong node features
__device__ float g_rn[N_EDGES * 3];             // -r / |r|
__device__ float g_bl[N_EDGES];                 // |r|
__device__ float g_ye[(size_t)N_EDGES * 192];   // y @ Wedge[l] + bedge[l], all 3 layers
__device__ float g_xnode[N_NODES * 128];        // [xj | xi] per node
__device__ float g_xij[(size_t)N_EDGES * DM_];
__device__ float g_ft[N_NODES * DM_];
// counting-sort of triplets by t_dst
__device__ int   g_cnt[N_EDGES + 1];            // offsets after scan
__device__ int   g_cur[N_EDGES];
__device__ int   g_tss[N_TRIP];                 // t_src permuted into t_dst-grouped order
__device__ int   g_bsum[128];

// ---------------- helpers ----------------
__device__ __forceinline__ float silu_f(float v) {
    return v * (1.0f / (1.0f + __expf(-v)));
}
__device__ __forceinline__ ull pk2(float x, float y) {
    ull r; asm("mov.b64 %0, {%1, %2};" : "=l"(r) : "f"(x), "f"(y)); return r;
}
__device__ __forceinline__ float2 up2(ull v) {
    float2 r; asm("mov.b64 {%0, %1}, %2;" : "=f"(r.x), "=f"(r.y) : "l"(v)); return r;
}
__device__ __forceinline__ void fma2(ull& d, ull a, ull b) {
    asm("fma.rn.f32x2 %0, %1, %2, %0;" : "+l"(d) : "l"(a), "l"(b));
}

// ---------------- setup kernels ----------------
__global__ void k_embed(const int* __restrict__ an, const float* __restrict__ emb) {
    int idx = blockIdx.x * 256 + threadIdx.x;
    if (idx >= N_NODES * D_) return;
    int n = idx >> 8, d = idx & 255;
    g_x[0][idx] = emb[an[n] * D_ + d];
}

__global__ void k_geom(const float* __restrict__ r) {
    int e = blockIdx.x * 256 + threadIdx.x;
    if (e >= N_EDGES) return;
    float x = r[e * 3], y = r[e * 3 + 1], z = r[e * 3 + 2];
    float bl = sqrtf(x * x + y * y + z * z);
    g_bl[e] = bl;
    float inv = -1.0f / bl;
    g_rn[e * 3] = x * inv; g_rn[e * 3 + 1] = y * inv; g_rn[e * 3 + 2] = z * inv;
}

// ---------------- counting sort of triplets by t_dst ----------------
__global__ void k_sort_zero() {
    int i = blockIdx.x * 256 + threadIdx.x;
    if (i <= N_EDGES) g_cnt[i] = 0;
    if (i < N_EDGES) g_cur[i] = 0;
}
__global__ void k_hist(const int* __restrict__ td) {
    int t = blockIdx.x * 256 + threadIdx.x;
    if (t < N_TRIP) atomicAdd(&g_cnt[td[t] + 1], 1);
}
// inclusive scan, blocks of 2048 (256 thr x 8)
__global__ void k_scanA() {
    __shared__ int sh[256];
    int tid = threadIdx.x;
    int base = blockIdx.x * 2048 + tid * 8;
    int v[8]; int s = 0;
#pragma unroll
    for (int q = 0; q < 8; q++) { int i = base + q; v[q] = (i <= N_EDGES) ? g_cnt[i] : 0; s += v[q]; }
    sh[tid] = s; __syncthreads();
    for (int off = 1; off < 256; off <<= 1) {
        int t2 = (tid >= off) ? sh[tid - off] : 0;
        __syncthreads();
        sh[tid] += t2;
        __syncthreads();
    }
    int run = (tid > 0) ? sh[tid - 1] : 0;
#pragma unroll
    for (int q = 0; q < 8; q++) { run += v[q]; int i = base + q; if (i <= N_EDGES) g_cnt[i] = run; }
    if (tid == 255) g_bsum[blockIdx.x] = sh[255];
}
__global__ void k_scanB(int nblk) {   // single block: exclusive scan of g_bsum
    __shared__ int sh[128];
    int tid = threadIdx.x;
    sh[tid] = (tid < nblk) ? g_bsum[tid] : 0;
    __syncthreads();
    for (int off = 1; off < 128; off <<= 1) {
        int t2 = (tid >= off) ? sh[tid - off] : 0;
        __syncthreads();
        sh[tid] += t2;
        __syncthreads();
    }
    if (tid < nblk) g_bsum[tid] = (tid > 0) ? sh[tid - 1] : 0;
}
__global__ void k_scanC() {
    int i = blockIdx.x * 256 + threadIdx.x;
    if (i <= N_EDGES) g_cnt[i] += g_bsum[i >> 11];
}
__global__ void k_scatter(const int* __restrict__ ts_, const int* __restrict__ td_) {
    int t = blockIdx.x * 256 + threadIdx.x;
    if (t >= N_TRIP) return;
    int td = __ldg(td_ + t);
    int p = g_cnt[td] + atomicAdd(&g_cur[td], 1);
    g_tss[p] = __ldg(ts_ + t);
}

// ---------------- per-layer kernels ----------------
// ye[e, l*64+k] = RBF(bl_e) . Wedge[l][:,k] + bedge[l][k] ; 32 edges/block, all 3 layers
__global__ void k_ye(const float* __restrict__ We, const float* __restrict__ be) {
    __shared__ float ys[D_ * 32];
    __shared__ float bls[32];
    int e0 = blockIdx.x * 32;
    int tid = threadIdx.x;          // 0..191
    if (tid < 32) bls[tid] = g_bl[e0 + tid];
    __syncthreads();
    for (int idx = tid; idx < 32 * D_; idx += 192) {
        int j = idx >> 8, d = idx & 255;
        float diff = bls[j] - (float)d * (8.0f / 255.0f);
        ys[d * 32 + j] = __expf(-1016.015625f * diff * diff);
    }
    __syncthreads();
    int l = tid / 64, kk = tid & 63;
    const float* W = We + l * (D_ * DM_) + kk;
    ull acc[16];
#pragma unroll
    for (int q = 0; q < 16; q++) acc[q] = 0ull;
    for (int d = 0; d < D_; d++) {
        float w = __ldg(W + d * DM_);
        ull wz = pk2(w, w);
        const ulonglong2* yv = (const ulonglong2*)(ys + d * 32);
#pragma unroll
        for (int q = 0; q < 8; q++) {
            ulonglong2 v = yv[q];
            fma2(acc[2 * q], v.x, wz);
            fma2(acc[2 * q + 1], v.y, wz);
        }
    }
    float b = __ldg(be + l * DM_ + kk);
#pragma unroll
    for (int q = 0; q < 16; q++) {
        float2 v = up2(acc[q]);
        g_ye[(size_t)(e0 + 2 * q) * 192 + tid]     = v.x + b;
        g_ye[(size_t)(e0 + 2 * q + 1) * 192 + tid] = v.y + b;
    }
}

// xnode[n][0:64] = x@Wsrc+bsrc ; xnode[n][64:128] = x@Wdst+bdst ; 8 nodes/block
__global__ void k_nodeproj(int cur, const float* __restrict__ Ws, const float* __restrict__ bs,
                           const float* __restrict__ Wd, const float* __restrict__ bd) {
    __shared__ float xs[D_ * 8];
    int n0 = blockIdx.x * 8, tid = threadIdx.x;
    const float* x = g_x[cur];
    for (int idx = tid; idx < 8 * D_; idx += 128) {
        int j = idx >> 8, d = idx & 255;
        xs[d * 8 + j] = x[(n0 + j) * D_ + d];
    }
    __syncthreads();
    const float* W = (tid < 64) ? Ws : Wd;
    int kk = tid & 63;
    float b = ((tid < 64) ? bs : bd)[kk];
    ull acc[4];
#pragma unroll
    for (int q = 0; q < 4; q++) acc[q] = 0ull;
    for (int d = 0; d < D_; d++) {
        float w = __ldg(W + d * DM_ + kk);
        ull wz = pk2(w, w);
        const ulonglong2* xv = (const ulonglong2*)(xs + d * 8);
#pragma unroll
        for (int q = 0; q < 2; q++) {
            ulonglong2 v = xv[q];
            fma2(acc[2 * q], v.x, wz);
            fma2(acc[2 * q + 1], v.y, wz);
        }
    }
#pragma unroll
    for (int q = 0; q < 4; q++) {
        float2 v = up2(acc[q]);
        g_xnode[(n0 + 2 * q) * 128 + tid]     = v.x + b;
        g_xnode[(n0 + 2 * q + 1) * 128 + tid] = v.y + b;
    }
}

__global__ void k_xij(const int* __restrict__ gs, const int* __restrict__ gd, int l) {
    int idx = blockIdx.x * 256 + threadIdx.x;      // one float4 per thread
    if (idx >= N_EDGES * 16) return;
    int e = idx >> 4, q = idx & 15;
    int s = __ldg(gs + e), d = __ldg(gd + e);
    float4 a = *(const float4*)&g_xnode[s * 128 + 4 * q];
    float4 b = *(const float4*)&g_xnode[d * 128 + 64 + 4 * q];
    float4 y = *(const float4*)&g_ye[(size_t)e * 192 + l * 64 + 4 * q];
    float4 o = make_float4(a.x + b.x + y.x, a.y + b.y + y.y, a.z + b.z + y.z, a.w + b.w + y.w);
    *(float4*)&g_xij[(size_t)e * DM_ + 4 * q] = o;
}

__global__ void k_initft() {
    int idx = blockIdx.x * 256 + threadIdx.x;
    if (idx < N_NODES * DM_) g_ft[idx] = 0.0f;
}

// One warp per destination edge: full softmax + attended message in registers,
// one red.v2 per edge into ft[node].
__global__ void k_trip(const int* __restrict__ gdst, const float* __restrict__ attn_l) {
    int e = blockIdx.x * 8 + (threadIdx.x >> 5);
    if (e >= N_EDGES) return;
    int lane = threadIdx.x & 31;
    int start = g_cnt[e], end = g_cnt[e + 1];
    if (start == end) return;
    float bx = g_rn[e * 3], by = g_rn[e * 3 + 1], bz = g_rn[e * 3 + 2];
    float2 xdv = *(const float2*)&g_xij[(size_t)e * DM_ + 2 * lane];
    float a0 = __ldg(attn_l + 2 * lane), a1 = __ldg(attn_l + 2 * lane + 1);
    float den = 0.0f, accx = 0.0f, accy = 0.0f;
    for (int i = start; i < end; i++) {
        int ts = g_tss[i];
        float ax = g_rn[ts * 3], ay = g_rn[ts * 3 + 1], az = g_rn[ts * 3 + 2];
        float c = ax * bx + ay * by + az * bz;
        c = fminf(1.0f, fmaxf(-1.0f, c));
        float s = sqrtf(fmaxf(0.0f, 1.0f - c * c));
        // Chebyshev T_k(c) = Re((c+is)^k) via binary exponentiation
        float r2 = c * c - s * s,         i2 = 2.0f * c * s;
        float r4 = r2 * r2 - i2 * i2,     i4 = 2.0f * r2 * i2;
        float r8 = r4 * r4 - i4 * i4,     i8 = 2.0f * r4 * i4;
        float r16 = r8 * r8 - i8 * i8,    i16 = 2.0f * r8 * i8;
        float r32 = r16 * r16 - i16 * i16, i32 = 2.0f * r16 * i16;
        float ur = (lane & 1) ? r2 : 1.0f;
        float ui = (lane & 1) ? i2 : 0.0f;
        {
            float qr = (lane & 2) ? r4 : 1.0f, qi = (lane & 2) ? i4 : 0.0f;
            float tr = ur * qr - ui * qi; ui = ur * qi + ui * qr; ur = tr;
        }
        {
            float qr = (lane & 4) ? r8 : 1.0f, qi = (lane & 4) ? i8 : 0.0f;
            float tr = ur * qr - ui * qi; ui = ur * qi + ui * qr; ur = tr;
        }
        {
            float qr = (lane & 8) ? r16 : 1.0f, qi = (lane & 8) ? i16 : 0.0f;
            float tr = ur * qr - ui * qi; ui = ur * qi + ui * qr; ur = tr;
        }
        {
            float qr = (lane & 16) ? r32 : 1.0f, qi = (lane & 16) ? i32 : 0.0f;
            float tr = ur * qr - ui * qi; ui = ur * qi + ui * qr; ur = tr;
        }
        float z0 = ur;               // cos(2*lane * theta)
        float z1 = ur * c - ui * s;  // cos((2*lane+1) * theta)
        float2 xsv = *(const float2*)&g_xij[(size_t)ts * DM_ + 2 * lane];
        float e0 = silu_f(z0 + xsv.x + xdv.x);
        float e1 = silu_f(z1 + xsv.y + xdv.y);
        float p = e0 * a0 + e1 * a1;
#pragma unroll
        for (int off = 16; off; off >>= 1) p += __shfl_xor_sync(0xffffffffu, p, off);
        float ex = __expf(p);        // max-shift elided; logits bounded
        den += ex;
        accx += ex * xsv.x;
        accy += ex * xsv.y;
    }
    int node = __ldg(gdst + e);
    float inv = 1.0f / den;
    float* p = &g_ft[node * DM_ + 2 * lane];
    asm volatile("red.global.add.v2.f32 [%0], {%1, %2};"
                 :: "l"(p), "f"(accx * inv), "f"(accy * inv) : "memory");
}

// fused FFN: x_out = silu(ft @ W1 + b1) @ W2 + b2   (64 -> 1024 -> 256)
__global__ void k_ffn(int nxt, const float* __restrict__ W1, const float* __restrict__ b1,
                      const float* __restrict__ W2, const float* __restrict__ b2) {
    __shared__ float fts[DM_ * 16];
    __shared__ float hs[512 * 16];
    int n0 = blockIdx.x * 16, tid = threadIdx.x;
    for (int idx = tid; idx < 16 * DM_; idx += 256) {
        int j = idx >> 6, d = idx & 63;
        fts[d * 16 + j] = g_ft[(n0 + j) * DM_ + d];
    }
    ull acc2[8];
#pragma unroll
    for (int q = 0; q < 8; q++) acc2[q] = 0ull;
    for (int ch = 0; ch < 2; ch++) {
        __syncthreads();
#pragma unroll
        for (int rep = 0; rep < 2; rep++) {
            int hl = rep * 256 + tid;
            int hh = ch * 512 + hl;
            ull acc[8];
#pragma unroll
            for (int q = 0; q < 8; q++) acc[q] = 0ull;
            for (int d = 0; d < DM_; d++) {
                float w = __ldg(W1 + d * H_ + hh);
                ull wz = pk2(w, w);
                const ulonglong2* fv = (const ulonglong2*)(fts + d * 16);
#pragma unroll
                for (int q = 0; q < 4; q++) {
                    ulonglong2 v = fv[q];
                    fma2(acc[2 * q], v.x, wz);
                    fma2(acc[2 * q + 1], v.y, wz);
                }
            }
            float bb = __ldg(b1 + hh);
            float2* hv = (float2*)(hs + hl * 16);
#pragma unroll
            for (int q = 0; q < 8; q++) {
                float2 v = up2(acc[q]);
                hv[q] = make_float2(silu_f(v.x + bb), silu_f(v.y + bb));
            }
        }
        __syncthreads();
        for (int hl = 0; hl < 512; hl++) {
            float w = __ldg(W2 + (ch * 512 + hl) * D_ + tid);
            ull wz = pk2(w, w);
            const ulonglong2* hv = (const ulonglong2*)(hs + hl * 16);
#pragma unroll
            for (int q = 0; q < 4; q++) {
                ulonglong2 v = hv[q];
                fma2(acc2[2 * q], v.x, wz);
                fma2(acc2[2 * q + 1], v.y, wz);
            }
        }
    }
    float bb = __ldg(b2 + tid);
    float* xo = g_x[nxt];
#pragma unroll
    for (int q = 0; q < 8; q++) {
        float2 v = up2(acc2[q]);
        xo[(n0 + 2 * q) * D_ + tid]     = v.x + bb;
        xo[(n0 + 2 * q + 1) * D_ + tid] = v.y + bb;
    }
}

__global__ void k_zero(float* out) {
    if (blockIdx.x == 0 && threadIdx.x == 0) out[0] = 0.0f;
}

__global__ void k_fc(int cur, const float* __restrict__ Wfc, const float* __restrict__ bfc,
                     float* out) {
    __shared__ float wf[D_];
    __shared__ float red[8];
    for (int i = threadIdx.x; i < D_; i += 256) wf[i] = Wfc[i];
    __syncthreads();
    const float* x = g_x[cur];
    float local = 0.0f;
    int stride = gridDim.x * 256;
    for (int idx = blockIdx.x * 256 + threadIdx.x; idx < N_NODES * D_; idx += stride)
        local += x[idx] * wf[idx & 255];
#pragma unroll
    for (int off = 16; off; off >>= 1) local += __shfl_xor_sync(0xffffffffu, local, off);
    if ((threadIdx.x & 31) == 0) red[threadIdx.x >> 5] = local;
    __syncthreads();
    if (threadIdx.x < 8) {
        float v = red[threadIdx.x];
#pragma unroll
        for (int off = 4; off; off >>= 1) v += __shfl_xor_sync(0xffu, v, off);
        if (threadIdx.x == 0) atomicAdd(out, v * (1.0f / (float)N_NODES));
    }
    if (blockIdx.x == 0 && threadIdx.x == 0) atomicAdd(out, __ldg(bfc));
}

// ---------------- host ----------------
extern "C" void kernel_launch(void* const* d_in, const int* in_sizes, int n_in,
                              void* d_out, int out_size) {
    const int*   an    = (const int*)d_in[0];
    const int*   gs    = (const int*)d_in[1];
    const int*   gd    = (const int*)d_in[2];
    const int*   tsp   = (const int*)d_in[3];
    const int*   tdp   = (const int*)d_in[4];
    const float* r     = (const float*)d_in[5];
    const float* emb   = (const float*)d_in[6];
    const float* Wsrc  = (const float*)d_in[7];
    const float* bsrc  = (const float*)d_in[8];
    const float* Wdst  = (const float*)d_in[9];
    const float* bdst  = (const float*)d_in[10];
    const float* Wedge = (const float*)d_in[11];
    const float* bedge = (const float*)d_in[12];
    const float* attn  = (const float*)d_in[13];
    const float* W1    = (const float*)d_in[14];
    const float* b1    = (const float*)d_in[15];
    const float* W2    = (const float*)d_in[16];
    const float* b2    = (const float*)d_in[17];
    const float* Wfc   = (const float*)d_in[18];
    const float* bfc   = (const float*)d_in[19];
    float* out = (float*)d_out;

    const int scan_blocks = (N_EDGES + 1 + 2047) / 2048;   // 79

    k_embed<<<(N_NODES * D_ + 255) / 256, 256>>>(an, emb);
    k_geom<<<(N_EDGES + 255) / 256, 256>>>(r);
    // counting sort of triplets by destination bond
    k_sort_zero<<<(N_EDGES + 256) / 256, 256>>>();
    k_hist<<<(N_TRIP + 255) / 256, 256>>>(tdp);
    k_scanA<<<scan_blocks, 256>>>();
    k_scanB<<<1, 128>>>(scan_blocks);
    k_scanC<<<(N_EDGES + 256) / 256, 256>>>();
    k_scatter<<<(N_TRIP + 255) / 256, 256>>>(tsp, tdp);
    // edge features for all 3 layers
    k_ye<<<N_EDGES / 32, 192>>>(Wedge, bedge);

    int cur = 0;
    for (int l = 0; l < L_; l++) {
        k_nodeproj<<<N_NODES / 8, 128>>>(cur, Wsrc + l * D_ * DM_, bsrc + l * DM_,
                                         Wdst + l * D_ * DM_, bdst + l * DM_);
        k_xij<<<(N_EDGES * 16 + 255) / 256, 256>>>(gs, gd, l);
        k_initft<<<(N_NODES * DM_ + 255) / 256, 256>>>();
        k_trip<<<(N_EDGES + 7) / 8, 256>>>(gd, attn + l * DM_);
        k_ffn<<<N_NODES / 16, 256>>>(1 - cur, W1 + l * DM_ * H_, b1 + l * H_,
                                     W2 + l * H_ * D_, b2 + l * D_);
        cur = 1 - cur;
    }
    k_zero<<<1, 1>>>(out);
    k_fc<<<256, 256>>>(cur, Wfc, bfc, out);
}

// round 4
// speedup vs baseline: 1.6042x; 1.1847x over previous
#include <cuda_runtime.h>
#include <math.h>

#define N_NODES 10000
#define N_EDGES 160000
#define N_TRIP  1200000
#define D_      256
#define DM_     64
#define H_      1024
#define L_      3
#define NB      32          // nodes per FFN block

typedef unsigned long long ull;

// ---------------- scratch (device globals; no allocation) ----------------
__device__ float g_x[2][N_NODES * D_];          // ping-pong node features
__device__ float g_rn[N_EDGES * 3];             // -r / |r|
__device__ float g_bl[N_EDGES];                 // |r|
__device__ float g_xnode[N_NODES * 128];        // [xj | xi] per node
__device__ float g_xij[(size_t)N_EDGES * DM_];
__device__ float g_ft[N_NODES * DM_];
// counting-sort of triplets by t_dst
__device__ int   g_cnt[N_EDGES + 1];
__device__ int   g_cur[N_EDGES];
__device__ int   g_tss[N_TRIP];
__device__ int   g_bsum[128];

// ---------------- helpers ----------------
__device__ __forceinline__ float silu_f(float v) {
    return v * (1.0f / (1.0f + __expf(-v)));
}
__device__ __forceinline__ ull pk2(float x, float y) {
    ull r; asm("mov.b64 %0, {%1, %2};" : "=l"(r) : "f"(x), "f"(y)); return r;
}
__device__ __forceinline__ float2 up2(ull v) {
    float2 r; asm("mov.b64 {%0, %1}, %2;" : "=f"(r.x), "=f"(r.y) : "l"(v)); return r;
}
__device__ __forceinline__ void fma2(ull& d, ull a, ull b) {
    asm("fma.rn.f32x2 %0, %1, %2, %0;" : "+l"(d) : "l"(a), "l"(b));
}

// ---------------- setup kernels ----------------
__global__ void k_embed(const int* __restrict__ an, const float* __restrict__ emb) {
    int idx = blockIdx.x * 256 + threadIdx.x;
    if (idx >= N_NODES * D_) return;
    int n = idx >> 8, d = idx & 255;
    g_x[0][idx] = emb[an[n] * D_ + d];
}

__global__ void k_geom(const float* __restrict__ r) {
    int e = blockIdx.x * 256 + threadIdx.x;
    if (e >= N_EDGES) return;
    float x = r[e * 3], y = r[e * 3 + 1], z = r[e * 3 + 2];
    float bl = sqrtf(x * x + y * y + z * z);
    g_bl[e] = bl;
    float inv = -1.0f / bl;
    g_rn[e * 3] = x * inv; g_rn[e * 3 + 1] = y * inv; g_rn[e * 3 + 2] = z * inv;
}

// ---------------- counting sort of triplets by t_dst ----------------
__global__ void k_sort_zero() {
    int i = blockIdx.x * 256 + threadIdx.x;
    if (i <= N_EDGES) g_cnt[i] = 0;
    if (i < N_EDGES) g_cur[i] = 0;
}
__global__ void k_hist(const int* __restrict__ td) {
    int t = blockIdx.x * 256 + threadIdx.x;
    if (t < N_TRIP) atomicAdd(&g_cnt[td[t] + 1], 1);
}
__global__ void k_scanA() {
    __shared__ int sh[256];
    int tid = threadIdx.x;
    int base = blockIdx.x * 2048 + tid * 8;
    int v[8]; int s = 0;
#pragma unroll
    for (int q = 0; q < 8; q++) { int i = base + q; v[q] = (i <= N_EDGES) ? g_cnt[i] : 0; s += v[q]; }
    sh[tid] = s; __syncthreads();
    for (int off = 1; off < 256; off <<= 1) {
        int t2 = (tid >= off) ? sh[tid - off] : 0;
        __syncthreads();
        sh[tid] += t2;
        __syncthreads();
    }
    int run = (tid > 0) ? sh[tid - 1] : 0;
#pragma unroll
    for (int q = 0; q < 8; q++) { run += v[q]; int i = base + q; if (i <= N_EDGES) g_cnt[i] = run; }
    if (tid == 255) g_bsum[blockIdx.x] = sh[255];
}
__global__ void k_scanB(int nblk) {
    __shared__ int sh[128];
    int tid = threadIdx.x;
    sh[tid] = (tid < nblk) ? g_bsum[tid] : 0;
    __syncthreads();
    for (int off = 1; off < 128; off <<= 1) {
        int t2 = (tid >= off) ? sh[tid - off] : 0;
        __syncthreads();
        sh[tid] += t2;
        __syncthreads();
    }
    if (tid < nblk) g_bsum[tid] = (tid > 0) ? sh[tid - 1] : 0;
}
__global__ void k_scanC() {
    int i = blockIdx.x * 256 + threadIdx.x;
    if (i <= N_EDGES) g_cnt[i] += g_bsum[i >> 11];
}
__global__ void k_scatter(const int* __restrict__ ts_, const int* __restrict__ td_) {
    int t = blockIdx.x * 256 + threadIdx.x;
    if (t >= N_TRIP) return;
    int td = __ldg(td_ + t);
    int p = g_cnt[td] + atomicAdd(&g_cur[td], 1);
    g_tss[p] = __ldg(ts_ + t);
}

// ---------------- per-layer kernels ----------------
// xnode[n][0:64] = x@Wsrc+bsrc ; xnode[n][64:128] = x@Wdst+bdst ; 8 nodes/block
__global__ void k_nodeproj(int cur, const float* __restrict__ Ws, const float* __restrict__ bs,
                           const float* __restrict__ Wd, const float* __restrict__ bd) {
    __shared__ float xs[D_ * 8];
    int n0 = blockIdx.x * 8, tid = threadIdx.x;
    const float* x = g_x[cur];
    for (int idx = tid; idx < 8 * D_; idx += 128) {
        int j = idx >> 8, d = idx & 255;
        xs[d * 8 + j] = x[(n0 + j) * D_ + d];
    }
    __syncthreads();
    const float* W = (tid < 64) ? Ws : Wd;
    int kk = tid & 63;
    float b = ((tid < 64) ? bs : bd)[kk];
    ull acc[4];
#pragma unroll
    for (int q = 0; q < 4; q++) acc[q] = 0ull;
    for (int d = 0; d < D_; d++) {
        float w = __ldg(W + d * DM_ + kk);
        ull wz = pk2(w, w);
        const ulonglong2* xv = (const ulonglong2*)(xs + d * 8);
#pragma unroll
        for (int q = 0; q < 2; q++) {
            ulonglong2 v = xv[q];
            fma2(acc[2 * q], v.x, wz);
            fma2(acc[2 * q + 1], v.y, wz);
        }
    }
#pragma unroll
    for (int q = 0; q < 4; q++) {
        float2 v = up2(acc[q]);
        g_xnode[(n0 + 2 * q) * 128 + tid]     = v.x + b;
        g_xnode[(n0 + 2 * q + 1) * 128 + tid] = v.y + b;
    }
}

// xij[e,k] = xnode[gs[e],k] + xnode[gd[e],64+k] + (RBF(bl_e) . Wedge[l])[k] + bedge[l][k]
// Sparse-tap RBF: gaussian with gamma=1016 is negligible beyond +-8 centers -> 17 taps.
// block: 256 threads = 4 edges x 64 cols
__global__ void k_exij(const int* __restrict__ gs, const int* __restrict__ gd,
                       const float* __restrict__ We_l, const float* __restrict__ be_l) {
    __shared__ float ys[4][20];
    int tid = threadIdx.x;
    int eL = tid >> 6, k = tid & 63;
    int e = blockIdx.x * 4 + eL;
    float bl = g_bl[e];
    int d0 = (int)floorf(bl * 31.875f + 0.5f);
    int lo = max(0, d0 - 8);
    int hi = min(255, d0 + 8);
    int cnt = hi - lo + 1;          // may be <= 0 if bl far out of range
    if (k < 17 && k < cnt) {
        float diff = bl - (float)(lo + k) * (8.0f / 255.0f);
        ys[eL][k] = __expf(-1016.015625f * diff * diff);
    }
    __syncthreads();
    float acc = __ldg(be_l + k);
    for (int t = 0; t < cnt; t++)
        acc = fmaf(ys[eL][t], __ldg(We_l + (lo + t) * DM_ + k), acc);
    int s = __ldg(gs + e), d = __ldg(gd + e);
    acc += g_xnode[s * 128 + k] + g_xnode[d * 128 + 64 + k];
    g_xij[(size_t)e * DM_ + k] = acc;
}

__global__ void k_initft() {
    int idx = blockIdx.x * 256 + threadIdx.x;
    if (idx < N_NODES * DM_) g_ft[idx] = 0.0f;
}

// per-triplet logit contribution (pre-reduction)
__device__ __forceinline__ void trip_body(int ts, float bx, float by, float bz,
                                          float xdx, float xdy, float a0, float a1, int lane,
                                          float& p, float& xsx, float& xsy) {
    float ax = __ldg(&g_rn[ts * 3]), ay = __ldg(&g_rn[ts * 3 + 1]), az = __ldg(&g_rn[ts * 3 + 2]);
    float c = ax * bx + ay * by + az * bz;
    c = fminf(1.0f, fmaxf(-1.0f, c));
    float s = sqrtf(fmaxf(0.0f, 1.0f - c * c));
    float r2 = c * c - s * s,          i2 = 2.0f * c * s;
    float r4 = r2 * r2 - i2 * i2,      i4 = 2.0f * r2 * i2;
    float r8 = r4 * r4 - i4 * i4,      i8 = 2.0f * r4 * i4;
    float r16 = r8 * r8 - i8 * i8,     i16 = 2.0f * r8 * i8;
    float r32 = r16 * r16 - i16 * i16, i32 = 2.0f * r16 * i16;
    float ur = (lane & 1) ? r2 : 1.0f;
    float ui = (lane & 1) ? i2 : 0.0f;
    {
        float qr = (lane & 2) ? r4 : 1.0f, qi = (lane & 2) ? i4 : 0.0f;
        float tr = ur * qr - ui * qi; ui = ur * qi + ui * qr; ur = tr;
    }
    {
        float qr = (lane & 4) ? r8 : 1.0f, qi = (lane & 4) ? i8 : 0.0f;
        float tr = ur * qr - ui * qi; ui = ur * qi + ui * qr; ur = tr;
    }
    {
        float qr = (lane & 8) ? r16 : 1.0f, qi = (lane & 8) ? i16 : 0.0f;
        float tr = ur * qr - ui * qi; ui = ur * qi + ui * qr; ur = tr;
    }
    {
        float qr = (lane & 16) ? r32 : 1.0f, qi = (lane & 16) ? i32 : 0.0f;
        float tr = ur * qr - ui * qi; ui = ur * qi + ui * qr; ur = tr;
    }
    float z0 = ur;               // cos(2*lane * theta)
    float z1 = ur * c - ui * s;  // cos((2*lane+1) * theta)
    float2 xsv = *(const float2*)&g_xij[(size_t)ts * DM_ + 2 * lane];
    float e0 = silu_f(z0 + xsv.x + xdx);
    float e1 = silu_f(z1 + xsv.y + xdy);
    p = e0 * a0 + e1 * a1;
    xsx = xsv.x; xsy = xsv.y;
}

// One warp per destination edge; softmax + attended message in registers.
// Unrolled by 2: two independent triplet chains, shfl reductions interleaved.
__global__ void k_trip(const int* __restrict__ gdst, const float* __restrict__ attn_l) {
    int e = blockIdx.x * 8 + (threadIdx.x >> 5);
    if (e >= N_EDGES) return;
    int lane = threadIdx.x & 31;
    int start = __ldg(&g_cnt[e]), end = __ldg(&g_cnt[e + 1]);
    if (start == end) return;
    float bx = g_rn[e * 3], by = g_rn[e * 3 + 1], bz = g_rn[e * 3 + 2];
    float2 xdv = *(const float2*)&g_xij[(size_t)e * DM_ + 2 * lane];
    float a0 = __ldg(attn_l + 2 * lane), a1 = __ldg(attn_l + 2 * lane + 1);
    float den = 0.0f, accx = 0.0f, accy = 0.0f;
    int i = start;
    for (; i + 2 <= end; i += 2) {
        int ts0 = __ldg(&g_tss[i]), ts1 = __ldg(&g_tss[i + 1]);
        float p0, x0, y0, p1, x1, y1;
        trip_body(ts0, bx, by, bz, xdv.x, xdv.y, a0, a1, lane, p0, x0, y0);
        trip_body(ts1, bx, by, bz, xdv.x, xdv.y, a0, a1, lane, p1, x1, y1);
#pragma unroll
        for (int off = 16; off; off >>= 1) {
            p0 += __shfl_xor_sync(0xffffffffu, p0, off);
            p1 += __shfl_xor_sync(0xffffffffu, p1, off);
        }
        float ex0 = __expf(p0), ex1 = __expf(p1);
        den += ex0 + ex1;
        accx += ex0 * x0 + ex1 * x1;
        accy += ex0 * y0 + ex1 * y1;
    }
    if (i < end) {
        int ts0 = __ldg(&g_tss[i]);
        float p0, x0, y0;
        trip_body(ts0, bx, by, bz, xdv.x, xdv.y, a0, a1, lane, p0, x0, y0);
#pragma unroll
        for (int off = 16; off; off >>= 1) p0 += __shfl_xor_sync(0xffffffffu, p0, off);
        float ex0 = __expf(p0);
        den += ex0; accx += ex0 * x0; accy += ex0 * y0;
    }
    int node = __ldg(gdst + e);
    float inv = 1.0f / den;
    float* p = &g_ft[node * DM_ + 2 * lane];
    asm volatile("red.global.add.v2.f32 [%0], {%1, %2};"
                 :: "l"(p), "f"(accx * inv), "f"(accy * inv) : "memory");
}

// fused FFN: x_out = silu(ft @ W1 + b1) @ W2 + b2   (64 -> 1024 -> 256), 32 nodes/block
__global__ void k_ffn(int nxt, const float* __restrict__ W1, const float* __restrict__ b1,
                      const float* __restrict__ W2, const float* __restrict__ b2) {
    extern __shared__ float sm[];
    float* fts = sm;                 // DM_*NB
    float* hs  = sm + DM_ * NB;      // 512*NB
    int n0 = blockIdx.x * NB, tid = threadIdx.x;
    for (int idx = tid; idx < NB * DM_; idx += 256) {
        int j = idx >> 6, d = idx & 63;
        fts[d * NB + j] = (n0 + j < N_NODES) ? g_ft[(n0 + j) * DM_ + d] : 0.0f;
    }
    ull acc2[NB / 2];
#pragma unroll
    for (int q = 0; q < NB / 2; q++) acc2[q] = 0ull;
    for (int ch = 0; ch < 2; ch++) {
        __syncthreads();
#pragma unroll
        for (int rep = 0; rep < 2; rep++) {
            int hl = rep * 256 + tid;
            int hh = ch * 512 + hl;
            ull acc[NB / 2];
#pragma unroll
            for (int q = 0; q < NB / 2; q++) acc[q] = 0ull;
            for (int d = 0; d < DM_; d++) {
                float w = __ldg(W1 + d * H_ + hh);
                ull wz = pk2(w, w);
                const ulonglong2* fv = (const ulonglong2*)(fts + d * NB);
#pragma unroll
                for (int q = 0; q < NB / 4; q++) {
                    ulonglong2 v = fv[q];
                    fma2(acc[2 * q], v.x, wz);
                    fma2(acc[2 * q + 1], v.y, wz);
                }
            }
            float bb = __ldg(b1 + hh);
            float2* hv = (float2*)(hs + hl * NB);
#pragma unroll
            for (int q = 0; q < NB / 2; q++) {
                float2 v = up2(acc[q]);
                hv[q] = make_float2(silu_f(v.x + bb), silu_f(v.y + bb));
            }
        }
        __syncthreads();
        for (int hl = 0; hl < 512; hl++) {
            float w = __ldg(W2 + (ch * 512 + hl) * D_ + tid);
            ull wz = pk2(w, w);
            const ulonglong2* hv = (const ulonglong2*)(hs + hl * NB);
#pragma unroll
            for (int q = 0; q < NB / 4; q++) {
                ulonglong2 v = hv[q];
                fma2(acc2[2 * q], v.x, wz);
                fma2(acc2[2 * q + 1], v.y, wz);
            }
        }
    }
    float bb = __ldg(b2 + tid);
    float* xo = g_x[nxt];
#pragma unroll
    for (int q = 0; q < NB / 2; q++) {
        float2 v = up2(acc2[q]);
        int ra = n0 + 2 * q, rb = ra + 1;
        if (ra < N_NODES) xo[ra * D_ + tid] = v.x + bb;
        if (rb < N_NODES) xo[rb * D_ + tid] = v.y + bb;
    }
}

__global__ void k_zero(float* out) {
    if (blockIdx.x == 0 && threadIdx.x == 0) out[0] = 0.0f;
}

__global__ void k_fc(int cur, const float* __restrict__ Wfc, const float* __restrict__ bfc,
                     float* out) {
    __shared__ float wf[D_];
    __shared__ float red[8];
    for (int i = threadIdx.x; i < D_; i += 256) wf[i] = Wfc[i];
    __syncthreads();
    const float* x = g_x[cur];
    float local = 0.0f;
    int stride = gridDim.x * 256;
    for (int idx = blockIdx.x * 256 + threadIdx.x; idx < N_NODES * D_; idx += stride)
        local += x[idx] * wf[idx & 255];
#pragma unroll
    for (int off = 16; off; off >>= 1) local += __shfl_xor_sync(0xffffffffu, local, off);
    if ((threadIdx.x & 31) == 0) red[threadIdx.x >> 5] = local;
    __syncthreads();
    if (threadIdx.x < 8) {
        float v = red[threadIdx.x];
#pragma unroll
        for (int off = 4; off; off >>= 1) v += __shfl_xor_sync(0xffu, v, off);
        if (threadIdx.x == 0) atomicAdd(out, v * (1.0f / (float)N_NODES));
    }
    if (blockIdx.x == 0 && threadIdx.x == 0) atomicAdd(out, __ldg(bfc));
}

// ---------------- host ----------------
extern "C" void kernel_launch(void* const* d_in, const int* in_sizes, int n_in,
                              void* d_out, int out_size) {
    const int*   an    = (const int*)d_in[0];
    const int*   gs    = (const int*)d_in[1];
    const int*   gd    = (const int*)d_in[2];
    const int*   tsp   = (const int*)d_in[3];
    const int*   tdp   = (const int*)d_in[4];
    const float* r     = (const float*)d_in[5];
    const float* emb   = (const float*)d_in[6];
    const float* Wsrc  = (const float*)d_in[7];
    const float* bsrc  = (const float*)d_in[8];
    const float* Wdst  = (const float*)d_in[9];
    const float* bdst  = (const float*)d_in[10];
    const float* Wedge = (const float*)d_in[11];
    const float* bedge = (const float*)d_in[12];
    const float* attn  = (const float*)d_in[13];
    const float* W1    = (const float*)d_in[14];
    const float* b1    = (const float*)d_in[15];
    const float* W2    = (const float*)d_in[16];
    const float* b2    = (const float*)d_in[17];
    const float* Wfc   = (const float*)d_in[18];
    const float* bfc   = (const float*)d_in[19];
    float* out = (float*)d_out;

    const int scan_blocks = (N_EDGES + 1 + 2047) / 2048;   // 79
    const int ffn_smem = (DM_ * NB + 512 * NB) * 4;        // 73728 B
    cudaFuncSetAttribute(k_ffn, cudaFuncAttributeMaxDynamicSharedMemorySize, ffn_smem);

    k_embed<<<(N_NODES * D_ + 255) / 256, 256>>>(an, emb);
    k_geom<<<(N_EDGES + 255) / 256, 256>>>(r);
    // counting sort of triplets by destination bond
    k_sort_zero<<<(N_EDGES + 256) / 256, 256>>>();
    k_hist<<<(N_TRIP + 255) / 256, 256>>>(tdp);
    k_scanA<<<scan_blocks, 256>>>();
    k_scanB<<<1, 128>>>(scan_blocks);
    k_scanC<<<(N_EDGES + 256) / 256, 256>>>();
    k_scatter<<<(N_TRIP + 255) / 256, 256>>>(tsp, tdp);

    int cur = 0;
    for (int l = 0; l < L_; l++) {
        k_nodeproj<<<N_NODES / 8, 128>>>(cur, Wsrc + l * D_ * DM_, bsrc + l * DM_,
                                         Wdst + l * D_ * DM_, bdst + l * DM_);
        k_exij<<<N_EDGES / 4, 256>>>(gs, gd, Wedge + l * D_ * DM_, bedge + l * DM_);
        k_initft<<<(N_NODES * DM_ + 255) / 256, 256>>>();
        k_trip<<<(N_EDGES + 7) / 8, 256>>>(gd, attn + l * DM_);
        k_ffn<<<(N_NODES + NB - 1) / NB, 256, ffn_smem>>>(1 - cur, W1 + l * DM_ * H_, b1 + l * H_,
                                                          W2 + l * H_ * D_, b2 + l * D_);
        cur = 1 - cur;
    }
    k_zero<<<1, 1>>>(out);
    k_fc<<<256, 256>>>(cur, Wfc, bfc, out);
}

// round 5
// speedup vs baseline: 1.6537x; 1.0308x over previous
#include <cuda_runtime.h>
#include <math.h>

#define N_NODES 10000
#define N_EDGES 160000
#define N_TRIP  1200000
#define D_      256
#define DM_     64
#define H_      1024
#define L_      3
#define NB      32          // nodes per FFN block

typedef unsigned long long ull;

// ---------------- scratch (device globals; no allocation) ----------------
__device__ float g_x[2][N_NODES * D_];          // ping-pong node features
__device__ float g_rn[N_EDGES * 3];             // -r / |r|
__device__ float g_bl[N_EDGES];                 // |r|
__device__ float g_xnode[N_NODES * 128];        // [xj | xi] per node
__device__ float g_xij[(size_t)N_EDGES * DM_];
__device__ float g_ft[N_NODES * DM_];
// counting-sort of triplets by t_dst
__device__ int   g_cnt[N_EDGES + 1];
__device__ int   g_cur[N_EDGES];
__device__ int   g_tss[N_TRIP];                 // sorted t_src
__device__ float g_css[N_TRIP];                 // sorted cos(theta), layer-invariant
__device__ float g_cosu[N_TRIP];                // unsorted cos
__device__ int   g_bsum[128];

// ---------------- helpers ----------------
__device__ __forceinline__ float silu_f(float v) {
    return v * (1.0f / (1.0f + __expf(-v)));
}
__device__ __forceinline__ ull pk2(float x, float y) {
    ull r; asm("mov.b64 %0, {%1, %2};" : "=l"(r) : "f"(x), "f"(y)); return r;
}
__device__ __forceinline__ float2 up2(ull v) {
    float2 r; asm("mov.b64 {%0, %1}, %2;" : "=f"(r.x), "=f"(r.y) : "l"(v)); return r;
}
__device__ __forceinline__ void fma2(ull& d, ull a, ull b) {
    asm("fma.rn.f32x2 %0, %1, %2, %0;" : "+l"(d) : "l"(a), "l"(b));
}

// ---------------- setup ----------------
// fused: node embedding + edge geometry + sort-count zeroing
__global__ void k_setup(const int* __restrict__ an, const float* __restrict__ emb,
                        const float* __restrict__ r) {
    int idx = blockIdx.x * 256 + threadIdx.x;
    if (idx < N_NODES * D_) {
        int n = idx >> 8, d = idx & 255;
        g_x[0][idx] = emb[an[n] * D_ + d];
    }
    if (idx < N_EDGES) {
        float x = r[idx * 3], y = r[idx * 3 + 1], z = r[idx * 3 + 2];
        float bl = sqrtf(x * x + y * y + z * z);
        g_bl[idx] = bl;
        float inv = -1.0f / bl;
        g_rn[idx * 3] = x * inv; g_rn[idx * 3 + 1] = y * inv; g_rn[idx * 3 + 2] = z * inv;
    }
    if (idx <= N_EDGES) g_cnt[idx] = 0;
    if (idx < N_EDGES) g_cur[idx] = 0;
}

// per-triplet cos(theta), layer-invariant; computed once, sorted with the triplets
__global__ void k_cos(const int* __restrict__ ts_, const int* __restrict__ td_) {
    int t = blockIdx.x * 256 + threadIdx.x;
    if (t >= N_TRIP) return;
    int a = __ldg(ts_ + t), b = __ldg(td_ + t);
    float c = g_rn[a * 3] * g_rn[b * 3] + g_rn[a * 3 + 1] * g_rn[b * 3 + 1]
            + g_rn[a * 3 + 2] * g_rn[b * 3 + 2];
    g_cosu[t] = fminf(1.0f, fmaxf(-1.0f, c));
}

__global__ void k_hist(const int* __restrict__ td) {
    int t = blockIdx.x * 256 + threadIdx.x;
    if (t < N_TRIP) atomicAdd(&g_cnt[td[t] + 1], 1);
}
__global__ void k_scanA() {
    __shared__ int sh[256];
    int tid = threadIdx.x;
    int base = blockIdx.x * 2048 + tid * 8;
    int v[8]; int s = 0;
#pragma unroll
    for (int q = 0; q < 8; q++) { int i = base + q; v[q] = (i <= N_EDGES) ? g_cnt[i] : 0; s += v[q]; }
    sh[tid] = s; __syncthreads();
    for (int off = 1; off < 256; off <<= 1) {
        int t2 = (tid >= off) ? sh[tid - off] : 0;
        __syncthreads();
        sh[tid] += t2;
        __syncthreads();
    }
    int run = (tid > 0) ? sh[tid - 1] : 0;
#pragma unroll
    for (int q = 0; q < 8; q++) { run += v[q]; int i = base + q; if (i <= N_EDGES) g_cnt[i] = run; }
    if (tid == 255) g_bsum[blockIdx.x] = sh[255];
}
__global__ void k_scanB(int nblk) {
    __shared__ int sh[128];
    int tid = threadIdx.x;
    sh[tid] = (tid < nblk) ? g_bsum[tid] : 0;
    __syncthreads();
    for (int off = 1; off < 128; off <<= 1) {
        int t2 = (tid >= off) ? sh[tid - off] : 0;
        __syncthreads();
        sh[tid] += t2;
        __syncthreads();
    }
    if (tid < nblk) g_bsum[tid] = (tid > 0) ? sh[tid - 1] : 0;
}
__global__ void k_scanC() {
    int i = blockIdx.x * 256 + threadIdx.x;
    if (i <= N_EDGES) g_cnt[i] += g_bsum[i >> 11];
}
__global__ void k_scatter(const int* __restrict__ ts_, const int* __restrict__ td_) {
    int t = blockIdx.x * 256 + threadIdx.x;
    if (t >= N_TRIP) return;
    int td = __ldg(td_ + t);
    int p = g_cnt[td] + atomicAdd(&g_cur[td], 1);
    g_tss[p] = __ldg(ts_ + t);
    g_css[p] = g_cosu[t];
}

// ---------------- per-layer kernels ----------------
__global__ void k_nodeproj(int cur, const float* __restrict__ Ws, const float* __restrict__ bs,
                           const float* __restrict__ Wd, const float* __restrict__ bd) {
    __shared__ float xs[D_ * 8];
    int n0 = blockIdx.x * 8, tid = threadIdx.x;
    const float* x = g_x[cur];
    for (int idx = tid; idx < 8 * D_; idx += 128) {
        int j = idx >> 8, d = idx & 255;
        xs[d * 8 + j] = x[(n0 + j) * D_ + d];
    }
    __syncthreads();
    const float* W = (tid < 64) ? Ws : Wd;
    int kk = tid & 63;
    float b = ((tid < 64) ? bs : bd)[kk];
    ull acc[4];
#pragma unroll
    for (int q = 0; q < 4; q++) acc[q] = 0ull;
    for (int d = 0; d < D_; d++) {
        float w = __ldg(W + d * DM_ + kk);
        ull wz = pk2(w, w);
        const ulonglong2* xv = (const ulonglong2*)(xs + d * 8);
#pragma unroll
        for (int q = 0; q < 2; q++) {
            ulonglong2 v = xv[q];
            fma2(acc[2 * q], v.x, wz);
            fma2(acc[2 * q + 1], v.y, wz);
        }
    }
#pragma unroll
    for (int q = 0; q < 4; q++) {
        float2 v = up2(acc[q]);
        g_xnode[(n0 + 2 * q) * 128 + tid]     = v.x + b;
        g_xnode[(n0 + 2 * q + 1) * 128 + tid] = v.y + b;
    }
}

// xij with sparse-tap RBF (17 taps), 4 edges x 64 cols per block
__global__ void k_exij(const int* __restrict__ gs, const int* __restrict__ gd,
                       const float* __restrict__ We_l, const float* __restrict__ be_l) {
    __shared__ float ys[4][20];
    int tid = threadIdx.x;
    int eL = tid >> 6, k = tid & 63;
    int e = blockIdx.x * 4 + eL;
    float bl = g_bl[e];
    int d0 = (int)floorf(bl * 31.875f + 0.5f);
    int lo = max(0, d0 - 8);
    int hi = min(255, d0 + 8);
    int cnt = hi - lo + 1;
    if (k < 17 && k < cnt) {
        float diff = bl - (float)(lo + k) * (8.0f / 255.0f);
        ys[eL][k] = __expf(-1016.015625f * diff * diff);
    }
    __syncthreads();
    float acc = __ldg(be_l + k);
    for (int t = 0; t < cnt; t++)
        acc = fmaf(ys[eL][t], __ldg(We_l + (lo + t) * DM_ + k), acc);
    int s = __ldg(gs + e), d = __ldg(gd + e);
    acc += g_xnode[s * 128 + k] + g_xnode[d * 128 + 64 + k];
    g_xij[(size_t)e * DM_ + k] = acc;
}

__global__ void k_initft() {
    int idx = blockIdx.x * 256 + threadIdx.x;
    if (idx < N_NODES * DM_) g_ft[idx] = 0.0f;
}

// per-triplet body: 4 channels per lane (lane16 in 0..15)
__device__ __forceinline__ void trip_body16(float c, int ts, int lane16,
                                            const float4& xd4, const float4& at4,
                                            float& p, float4& xs4) {
    float s = sqrtf(fmaxf(0.0f, 1.0f - c * c));
    float r4r, r4i;                                      // w^4
    {
        float r2r = c * c - s * s, r2i = 2.0f * c * s;
        r4r = r2r * r2r - r2i * r2i; r4i = 2.0f * r2r * r2i;
    }
    float r8r = r4r * r4r - r4i * r4i,   r8i = 2.0f * r4r * r4i;
    float r16r = r8r * r8r - r8i * r8i,  r16i = 2.0f * r8r * r8i;
    float r32r = r16r * r16r - r16i * r16i, r32i = 2.0f * r16r * r16i;
    // w^(4*lane16): bits 0..3 of lane16 select w^4, w^8, w^16, w^32
    float ur = (lane16 & 1) ? r4r : 1.0f;
    float ui = (lane16 & 1) ? r4i : 0.0f;
    {
        float qr = (lane16 & 2) ? r8r : 1.0f, qi = (lane16 & 2) ? r8i : 0.0f;
        float tr = ur * qr - ui * qi; ui = ur * qi + ui * qr; ur = tr;
    }
    {
        float qr = (lane16 & 4) ? r16r : 1.0f, qi = (lane16 & 4) ? r16i : 0.0f;
        float tr = ur * qr - ui * qi; ui = ur * qi + ui * qr; ur = tr;
    }
    {
        float qr = (lane16 & 8) ? r32r : 1.0f, qi = (lane16 & 8) ? r32i : 0.0f;
        float tr = ur * qr - ui * qi; ui = ur * qi + ui * qr; ur = tr;
    }
    float z0 = ur;                      // T_{4l}
    float z1 = ur * c - ui * s;         // T_{4l+1}
    float c2 = 2.0f * c;
    float z2 = c2 * z1 - z0;            // T_{4l+2}
    float z3 = c2 * z2 - z1;            // T_{4l+3}
    xs4 = *(const float4*)&g_xij[(size_t)ts * DM_ + 4 * (threadIdx.x & 15)];
    float e0 = silu_f(z0 + xs4.x + xd4.x);
    float e1 = silu_f(z1 + xs4.y + xd4.y);
    float e2 = silu_f(z2 + xs4.z + xd4.z);
    float e3 = silu_f(z3 + xs4.w + xd4.w);
    p = e0 * at4.x + e1 * at4.y + e2 * at4.z + e3 * at4.w;
}

// 16 lanes per destination edge (2 edges/warp); softmax + attended message in regs
__global__ void k_trip(const int* __restrict__ gdst, const float* __restrict__ attn_l) {
    int e = blockIdx.x * 16 + (threadIdx.x >> 4);
    if (e >= N_EDGES) return;
    int lane16 = threadIdx.x & 15;
    int start = __ldg(&g_cnt[e]), end = __ldg(&g_cnt[e + 1]);
    if (start == end) return;
    float4 xd4 = *(const float4*)&g_xij[(size_t)e * DM_ + 4 * lane16];
    float4 at4 = *(const float4*)&attn_l[4 * lane16];
    float den = 0.0f;
    float4 acc = make_float4(0.0f, 0.0f, 0.0f, 0.0f);
    int i = start;
    for (; i + 2 <= end; i += 2) {
        int ts0 = __ldg(&g_tss[i]), ts1 = __ldg(&g_tss[i + 1]);
        float c0 = __ldg(&g_css[i]), c1 = __ldg(&g_css[i + 1]);
        float p0, p1; float4 x0, x1;
        trip_body16(c0, ts0, lane16, xd4, at4, p0, x0);
        trip_body16(c1, ts1, lane16, xd4, at4, p1, x1);
#pragma unroll
        for (int off = 8; off; off >>= 1) {
            p0 += __shfl_xor_sync(0xffffffffu, p0, off);
            p1 += __shfl_xor_sync(0xffffffffu, p1, off);
        }
        float ex0 = __expf(p0), ex1 = __expf(p1);
        den += ex0 + ex1;
        acc.x += ex0 * x0.x + ex1 * x1.x;
        acc.y += ex0 * x0.y + ex1 * x1.y;
        acc.z += ex0 * x0.z + ex1 * x1.z;
        acc.w += ex0 * x0.w + ex1 * x1.w;
    }
    if (i < end) {
        int ts0 = __ldg(&g_tss[i]);
        float c0 = __ldg(&g_css[i]);
        float p0; float4 x0;
        trip_body16(c0, ts0, lane16, xd4, at4, p0, x0);
#pragma unroll
        for (int off = 8; off; off >>= 1) p0 += __shfl_xor_sync(0xffffffffu, p0, off);
        float ex0 = __expf(p0);
        den += ex0;
        acc.x += ex0 * x0.x; acc.y += ex0 * x0.y;
        acc.z += ex0 * x0.z; acc.w += ex0 * x0.w;
    }
    int node = __ldg(gdst + e);
    float inv = 1.0f / den;
    float* p = &g_ft[node * DM_ + 4 * lane16];
    asm volatile("red.global.add.v4.f32 [%0], {%1, %2, %3, %4};"
                 :: "l"(p), "f"(acc.x * inv), "f"(acc.y * inv),
                    "f"(acc.z * inv), "f"(acc.w * inv) : "memory");
}

// fused FFN: x_out = silu(ft @ W1 + b1) @ W2 + b2   (64 -> 1024 -> 256), 32 nodes/block
__global__ void k_ffn(int nxt, const float* __restrict__ W1, const float* __restrict__ b1,
                      const float* __restrict__ W2, const float* __restrict__ b2) {
    extern __shared__ float sm[];
    float* fts = sm;                 // DM_*NB
    float* hs  = sm + DM_ * NB;      // 512*NB
    int n0 = blockIdx.x * NB, tid = threadIdx.x;
    for (int idx = tid; idx < NB * DM_; idx += 256) {
        int j = idx >> 6, d = idx & 63;
        fts[d * NB + j] = (n0 + j < N_NODES) ? g_ft[(n0 + j) * DM_ + d] : 0.0f;
    }
    ull acc2[NB / 2];
#pragma unroll
    for (int q = 0; q < NB / 2; q++) acc2[q] = 0ull;
    for (int ch = 0; ch < 2; ch++) {
        __syncthreads();
#pragma unroll
        for (int rep = 0; rep < 2; rep++) {
            int hl = rep * 256 + tid;
            int hh = ch * 512 + hl;
            ull acc[NB / 2];
#pragma unroll
            for (int q = 0; q < NB / 2; q++) acc[q] = 0ull;
            for (int d = 0; d < DM_; d++) {
                float w = __ldg(W1 + d * H_ + hh);
                ull wz = pk2(w, w);
                const ulonglong2* fv = (const ulonglong2*)(fts + d * NB);
#pragma unroll
                for (int q = 0; q < NB / 4; q++) {
                    ulonglong2 v = fv[q];
                    fma2(acc[2 * q], v.x, wz);
                    fma2(acc[2 * q + 1], v.y, wz);
                }
            }
            float bb = __ldg(b1 + hh);
            float2* hv = (float2*)(hs + hl * NB);
#pragma unroll
            for (int q = 0; q < NB / 2; q++) {
                float2 v = up2(acc[q]);
                hv[q] = make_float2(silu_f(v.x + bb), silu_f(v.y + bb));
            }
        }
        __syncthreads();
        for (int hl = 0; hl < 512; hl++) {
            float w = __ldg(W2 + (ch * 512 + hl) * D_ + tid);
            ull wz = pk2(w, w);
            const ulonglong2* hv = (const ulonglong2*)(hs + hl * NB);
#pragma unroll
            for (int q = 0; q < NB / 4; q++) {
                ulonglong2 v = hv[q];
                fma2(acc2[2 * q], v.x, wz);
                fma2(acc2[2 * q + 1], v.y, wz);
            }
        }
    }
    float bb = __ldg(b2 + tid);
    float* xo = g_x[nxt];
#pragma unroll
    for (int q = 0; q < NB / 2; q++) {
        float2 v = up2(acc2[q]);
        int ra = n0 + 2 * q, rb = ra + 1;
        if (ra < N_NODES) xo[ra * D_ + tid] = v.x + bb;
        if (rb < N_NODES) xo[rb * D_ + tid] = v.y + bb;
    }
}

__global__ void k_zero(float* out) {
    if (blockIdx.x == 0 && threadIdx.x == 0) out[0] = 0.0f;
}

__global__ void k_fc(int cur, const float* __restrict__ Wfc, const float* __restrict__ bfc,
                     float* out) {
    __shared__ float wf[D_];
    __shared__ float red[8];
    for (int i = threadIdx.x; i < D_; i += 256) wf[i] = Wfc[i];
    __syncthreads();
    const float* x = g_x[cur];
    float local = 0.0f;
    int stride = gridDim.x * 256;
    for (int idx = blockIdx.x * 256 + threadIdx.x; idx < N_NODES * D_; idx += stride)
        local += x[idx] * wf[idx & 255];
#pragma unroll
    for (int off = 16; off; off >>= 1) local += __shfl_xor_sync(0xffffffffu, local, off);
    if ((threadIdx.x & 31) == 0) red[threadIdx.x >> 5] = local;
    __syncthreads();
    if (threadIdx.x < 8) {
        float v = red[threadIdx.x];
#pragma unroll
        for (int off = 4; off; off >>= 1) v += __shfl_xor_sync(0xffu, v, off);
        if (threadIdx.x == 0) atomicAdd(out, v * (1.0f / (float)N_NODES));
    }
    if (blockIdx.x == 0 && threadIdx.x == 0) atomicAdd(out, __ldg(bfc));
}

// ---------------- host ----------------
extern "C" void kernel_launch(void* const* d_in, const int* in_sizes, int n_in,
                              void* d_out, int out_size) {
    const int*   an    = (const int*)d_in[0];
    const int*   gs    = (const int*)d_in[1];
    const int*   gd    = (const int*)d_in[2];
    const int*   tsp   = (const int*)d_in[3];
    const int*   tdp   = (const int*)d_in[4];
    const float* r     = (const float*)d_in[5];
    const float* emb   = (const float*)d_in[6];
    const float* Wsrc  = (const float*)d_in[7];
    const float* bsrc  = (const float*)d_in[8];
    const float* Wdst  = (const float*)d_in[9];
    const float* bdst  = (const float*)d_in[10];
    const float* Wedge = (const float*)d_in[11];
    const float* bedge = (const float*)d_in[12];
    const float* attn  = (const float*)d_in[13];
    const float* W1    = (const float*)d_in[14];
    const float* b1    = (const float*)d_in[15];
    const float* W2    = (const float*)d_in[16];
    const float* b2    = (const float*)d_in[17];
    const float* Wfc   = (const float*)d_in[18];
    const float* bfc   = (const float*)d_in[19];
    float* out = (float*)d_out;

    const int scan_blocks = (N_EDGES + 1 + 2047) / 2048;   // 79
    const int ffn_smem = (DM_ * NB + 512 * NB) * 4;        // 73728 B
    cudaFuncSetAttribute(k_ffn, cudaFuncAttributeMaxDynamicSharedMemorySize, ffn_smem);

    k_setup<<<(N_NODES * D_ + 255) / 256, 256>>>(an, emb, r);
    k_cos<<<(N_TRIP + 255) / 256, 256>>>(tsp, tdp);
    k_hist<<<(N_TRIP + 255) / 256, 256>>>(tdp);
    k_scanA<<<scan_blocks, 256>>>();
    k_scanB<<<1, 128>>>(scan_blocks);
    k_scanC<<<(N_EDGES + 256) / 256, 256>>>();
    k_scatter<<<(N_TRIP + 255) / 256, 256>>>(tsp, tdp);

    int cur = 0;
    for (int l = 0; l < L_; l++) {
        k_nodeproj<<<N_NODES / 8, 128>>>(cur, Wsrc + l * D_ * DM_, bsrc + l * DM_,
                                         Wdst + l * D_ * DM_, bdst + l * DM_);
        k_exij<<<N_EDGES / 4, 256>>>(gs, gd, Wedge + l * D_ * DM_, bedge + l * DM_);
        k_initft<<<(N_NODES * DM_ + 255) / 256, 256>>>();
        k_trip<<<(N_EDGES + 15) / 16, 256>>>(gd, attn + l * DM_);
        k_ffn<<<(N_NODES + NB - 1) / NB, 256, ffn_smem>>>(1 - cur, W1 + l * DM_ * H_, b1 + l * H_,
                                                          W2 + l * H_ * D_, b2 + l * D_);
        cur = 1 - cur;
    }
    k_zero<<<1, 1>>>(out);
    k_fc<<<256, 256>>>(cur, Wfc, bfc, out);
}

// round 6
// speedup vs baseline: 1.7058x; 1.0315x over previous
#include <cuda_runtime.h>
#include <math.h>
#include <mma.h>

using namespace nvcuda;

#define N_NODES 10000
#define N_EDGES 160000
#define N_TRIP  1200000
#define D_      256
#define DM_     64
#define H_      1024
#define L_      3
#define FNB     32          // nodes per FFN block

typedef unsigned long long ull;

// ---------------- scratch (device globals; no allocation) ----------------
__device__ float g_x[2][N_NODES * D_];          // ping-pong node features
__device__ float g_rn[N_EDGES * 3];             // -r / |r|
__device__ float g_bl[N_EDGES];                 // |r|
__device__ float g_xnode[N_NODES * 128];        // [xj | xi] per node
__device__ float g_xij[(size_t)N_EDGES * DM_];
__device__ float g_ft[N_NODES * DM_];
// counting-sort of triplets by t_dst
__device__ int   g_cnt[N_EDGES + 1];
__device__ int   g_cur[N_EDGES];
__device__ int   g_tss[N_TRIP];                 // sorted t_src
__device__ float g_css[N_TRIP];                 // sorted cos(theta), layer-invariant
__device__ int   g_bsum[128];

// ---------------- helpers ----------------
__device__ __forceinline__ float silu_f(float v) {
    return v * (1.0f / (1.0f + __expf(-v)));
}
__device__ __forceinline__ ull pk2(float x, float y) {
    ull r; asm("mov.b64 %0, {%1, %2};" : "=l"(r) : "f"(x), "f"(y)); return r;
}
__device__ __forceinline__ float2 up2(ull v) {
    float2 r; asm("mov.b64 {%0, %1}, %2;" : "=f"(r.x), "=f"(r.y) : "l"(v)); return r;
}
__device__ __forceinline__ void fma2(ull& d, ull a, ull b) {
    asm("fma.rn.f32x2 %0, %1, %2, %0;" : "+l"(d) : "l"(a), "l"(b));
}

// ---------------- setup ----------------
__global__ void k_setup(const int* __restrict__ an, const float* __restrict__ emb,
                        const float* __restrict__ r) {
    int idx = blockIdx.x * 256 + threadIdx.x;
    if (idx < N_NODES * D_) {
        int n = idx >> 8, d = idx & 255;
        g_x[0][idx] = emb[an[n] * D_ + d];
    }
    if (idx < N_EDGES) {
        float x = r[idx * 3], y = r[idx * 3 + 1], z = r[idx * 3 + 2];
        float bl = sqrtf(x * x + y * y + z * z);
        g_bl[idx] = bl;
        float inv = -1.0f / bl;
        g_rn[idx * 3] = x * inv; g_rn[idx * 3 + 1] = y * inv; g_rn[idx * 3 + 2] = z * inv;
    }
    if (idx <= N_EDGES) g_cnt[idx] = 0;
    if (idx < N_EDGES) g_cur[idx] = 0;
}

__global__ void k_hist(const int* __restrict__ td) {
    int t = blockIdx.x * 256 + threadIdx.x;
    if (t < N_TRIP) atomicAdd(&g_cnt[td[t] + 1], 1);
}
__global__ void k_scanA() {
    __shared__ int sh[256];
    int tid = threadIdx.x;
    int base = blockIdx.x * 2048 + tid * 8;
    int v[8]; int s = 0;
#pragma unroll
    for (int q = 0; q < 8; q++) { int i = base + q; v[q] = (i <= N_EDGES) ? g_cnt[i] : 0; s += v[q]; }
    sh[tid] = s; __syncthreads();
    for (int off = 1; off < 256; off <<= 1) {
        int t2 = (tid >= off) ? sh[tid - off] : 0;
        __syncthreads();
        sh[tid] += t2;
        __syncthreads();
    }
    int run = (tid > 0) ? sh[tid - 1] : 0;
#pragma unroll
    for (int q = 0; q < 8; q++) { run += v[q]; int i = base + q; if (i <= N_EDGES) g_cnt[i] = run; }
    if (tid == 255) g_bsum[blockIdx.x] = sh[255];
}
__global__ void k_scanB(int nblk) {
    __shared__ int sh[128];
    int tid = threadIdx.x;
    sh[tid] = (tid < nblk) ? g_bsum[tid] : 0;
    __syncthreads();
    for (int off = 1; off < 128; off <<= 1) {
        int t2 = (tid >= off) ? sh[tid - off] : 0;
        __syncthreads();
        sh[tid] += t2;
        __syncthreads();
    }
    if (tid < nblk) g_bsum[tid] = (tid > 0) ? sh[tid - 1] : 0;
}
__global__ void k_scanC() {
    int i = blockIdx.x * 256 + threadIdx.x;
    if (i <= N_EDGES) g_cnt[i] += g_bsum[i >> 11];
}
// scatter + fused cos(theta) computation (layer-invariant)
__global__ void k_scatter(const int* __restrict__ ts_, const int* __restrict__ td_) {
    int t = blockIdx.x * 256 + threadIdx.x;
    if (t >= N_TRIP) return;
    int a = __ldg(ts_ + t), td = __ldg(td_ + t);
    float c = g_rn[a * 3] * g_rn[td * 3] + g_rn[a * 3 + 1] * g_rn[td * 3 + 1]
            + g_rn[a * 3 + 2] * g_rn[td * 3 + 2];
    c = fminf(1.0f, fmaxf(-1.0f, c));
    int p = g_cnt[td] + atomicAdd(&g_cur[td], 1);
    g_tss[p] = a;
    g_css[p] = c;
}

// ---------------- per-layer kernels ----------------
__global__ void k_nodeproj(int cur, const float* __restrict__ Ws, const float* __restrict__ bs,
                           const float* __restrict__ Wd, const float* __restrict__ bd) {
    __shared__ float xs[D_ * 8];
    int n0 = blockIdx.x * 8, tid = threadIdx.x;
    const float* x = g_x[cur];
    for (int idx = tid; idx < 8 * D_; idx += 128) {
        int j = idx >> 8, d = idx & 255;
        xs[d * 8 + j] = x[(n0 + j) * D_ + d];
    }
    __syncthreads();
    const float* W = (tid < 64) ? Ws : Wd;
    int kk = tid & 63;
    float b = ((tid < 64) ? bs : bd)[kk];
    ull acc[4];
#pragma unroll
    for (int q = 0; q < 4; q++) acc[q] = 0ull;
    for (int d = 0; d < D_; d++) {
        float w = __ldg(W + d * DM_ + kk);
        ull wz = pk2(w, w);
        const ulonglong2* xv = (const ulonglong2*)(xs + d * 8);
#pragma unroll
        for (int q = 0; q < 2; q++) {
            ulonglong2 v = xv[q];
            fma2(acc[2 * q], v.x, wz);
            fma2(acc[2 * q + 1], v.y, wz);
        }
    }
#pragma unroll
    for (int q = 0; q < 4; q++) {
        float2 v = up2(acc[q]);
        g_xnode[(n0 + 2 * q) * 128 + tid]     = v.x + b;
        g_xnode[(n0 + 2 * q + 1) * 128 + tid] = v.y + b;
    }
}

// xij with sparse-tap RBF (17 taps), 4 edges x 64 cols per block
__global__ void k_exij(const int* __restrict__ gs, const int* __restrict__ gd,
                       const float* __restrict__ We_l, const float* __restrict__ be_l) {
    __shared__ float ys[4][20];
    int tid = threadIdx.x;
    int eL = tid >> 6, k = tid & 63;
    int e = blockIdx.x * 4 + eL;
    float bl = g_bl[e];
    int d0 = (int)floorf(bl * 31.875f + 0.5f);
    int lo = max(0, d0 - 8);
    int hi = min(255, d0 + 8);
    int cnt = hi - lo + 1;
    if (k < 17 && k < cnt) {
        float diff = bl - (float)(lo + k) * (8.0f / 255.0f);
        ys[eL][k] = __expf(-1016.015625f * diff * diff);
    }
    __syncthreads();
    float acc = __ldg(be_l + k);
    for (int t = 0; t < cnt; t++)
        acc = fmaf(ys[eL][t], __ldg(We_l + (lo + t) * DM_ + k), acc);
    int s = __ldg(gs + e), d = __ldg(gd + e);
    acc += g_xnode[s * 128 + k] + g_xnode[d * 128 + 64 + k];
    g_xij[(size_t)e * DM_ + k] = acc;
}

__global__ void k_initft() {
    int idx = blockIdx.x * 256 + threadIdx.x;
    if (idx < N_NODES * DM_) g_ft[idx] = 0.0f;
}

// per-triplet logit: 4 Chebyshev channels per lane (data pre-loaded)
__device__ __forceinline__ float trip_logit(float c, const float4& xs4, const float4& xd4,
                                            const float4& at4, int lane16) {
    float s = sqrtf(fmaxf(0.0f, 1.0f - c * c));
    float r4r, r4i;
    {
        float r2r = c * c - s * s, r2i = 2.0f * c * s;
        r4r = r2r * r2r - r2i * r2i; r4i = 2.0f * r2r * r2i;
    }
    float r8r = r4r * r4r - r4i * r4i,      r8i = 2.0f * r4r * r4i;
    float r16r = r8r * r8r - r8i * r8i,     r16i = 2.0f * r8r * r8i;
    float r32r = r16r * r16r - r16i * r16i, r32i = 2.0f * r16r * r16i;
    float ur = (lane16 & 1) ? r4r : 1.0f;
    float ui = (lane16 & 1) ? r4i : 0.0f;
    {
        float qr = (lane16 & 2) ? r8r : 1.0f, qi = (lane16 & 2) ? r8i : 0.0f;
        float tr = ur * qr - ui * qi; ui = ur * qi + ui * qr; ur = tr;
    }
    {
        float qr = (lane16 & 4) ? r16r : 1.0f, qi = (lane16 & 4) ? r16i : 0.0f;
        float tr = ur * qr - ui * qi; ui = ur * qi + ui * qr; ur = tr;
    }
    {
        float qr = (lane16 & 8) ? r32r : 1.0f, qi = (lane16 & 8) ? r32i : 0.0f;
        float tr = ur * qr - ui * qi; ui = ur * qi + ui * qr; ur = tr;
    }
    float z0 = ur;
    float z1 = ur * c - ui * s;
    float c2 = 2.0f * c;
    float z2 = c2 * z1 - z0;
    float z3 = c2 * z2 - z1;
    float e0 = silu_f(z0 + xs4.x + xd4.x);
    float e1 = silu_f(z1 + xs4.y + xd4.y);
    float e2 = silu_f(z2 + xs4.z + xd4.z);
    float e3 = silu_f(z3 + xs4.w + xd4.w);
    return e0 * at4.x + e1 * at4.y + e2 * at4.z + e3 * at4.w;
}

// 16 lanes per destination edge (2 edges/warp).
// Convergent: both halves loop mp = max(pairs) times, invalid iterations masked.
// Software pipelined: next pair's loads issued before current pair's compute.
__global__ void k_trip(const int* __restrict__ gdst, const float* __restrict__ attn_l) {
    int tid = threadIdx.x;
    int e = blockIdx.x * 16 + (tid >> 4);       // grid is exactly N_EDGES/16
    int lane16 = tid & 15;
    int start = __ldg(&g_cnt[e]), end = __ldg(&g_cnt[e + 1]);
    int n = end - start;
    int npairs = (n + 1) >> 1;
    int op = __shfl_xor_sync(0xffffffffu, npairs, 16);
    int mp = max(npairs, op);
    if (mp == 0) return;                        // uniform across warp
    float4 xd4 = *(const float4*)&g_xij[(size_t)e * DM_ + 4 * lane16];
    float4 at4 = *(const float4*)&attn_l[4 * lane16];
    float den = 0.0f;
    float4 acc = make_float4(0.0f, 0.0f, 0.0f, 0.0f);
    int i0 = min(start, N_TRIP - 1), i1 = min(start + 1, N_TRIP - 1);
    int   tsA = __ldg(&g_tss[i0]); float cA = __ldg(&g_css[i0]);
    int   tsB = __ldg(&g_tss[i1]); float cB = __ldg(&g_css[i1]);
    float4 xA = *(const float4*)&g_xij[(size_t)tsA * DM_ + 4 * lane16];
    float4 xB = *(const float4*)&g_xij[(size_t)tsB * DM_ + 4 * lane16];
    for (int k = 0; k < mp; k++) {
        bool vA = (start + 2 * k) < end;
        bool vB = (start + 2 * k + 1) < end;
        // prefetch next pair
        int j0 = min(start + 2 * k + 2, N_TRIP - 1);
        int j1 = min(start + 2 * k + 3, N_TRIP - 1);
        int   ntsA = __ldg(&g_tss[j0]); float ncA = __ldg(&g_css[j0]);
        int   ntsB = __ldg(&g_tss[j1]); float ncB = __ldg(&g_css[j1]);
        float4 nxA = *(const float4*)&g_xij[(size_t)ntsA * DM_ + 4 * lane16];
        float4 nxB = *(const float4*)&g_xij[(size_t)ntsB * DM_ + 4 * lane16];
        // compute current pair
        float p0 = trip_logit(cA, xA, xd4, at4, lane16);
        float p1 = trip_logit(cB, xB, xd4, at4, lane16);
#pragma unroll
        for (int off = 8; off; off >>= 1) {
            p0 += __shfl_xor_sync(0xffffffffu, p0, off);
            p1 += __shfl_xor_sync(0xffffffffu, p1, off);
        }
        float ex0 = vA ? __expf(p0) : 0.0f;
        float ex1 = vB ? __expf(p1) : 0.0f;
        den += ex0 + ex1;
        acc.x += ex0 * xA.x + ex1 * xB.x;
        acc.y += ex0 * xA.y + ex1 * xB.y;
        acc.z += ex0 * xA.z + ex1 * xB.z;
        acc.w += ex0 * xA.w + ex1 * xB.w;
        tsA = ntsA; cA = ncA; xA = nxA;
        tsB = ntsB; cB = ncB; xB = nxB;
    }
    if (n > 0) {
        int node = __ldg(gdst + e);
        float inv = 1.0f / den;
        float* p = &g_ft[node * DM_ + 4 * lane16];
        asm volatile("red.global.add.v4.f32 [%0], {%1, %2, %3, %4};"
                     :: "l"(p), "f"(acc.x * inv), "f"(acc.y * inv),
                        "f"(acc.z * inv), "f"(acc.w * inv) : "memory");
    }
}

// fused FFN on tf32 tensor cores: x_out = silu(ft @ W1 + b1) @ W2 + b2
// block: 256 threads (8 warps), 32 nodes; hidden processed in 4 chunks of 256
#define LDA 72
#define LDH 264
__global__ void k_ffn(int nxt, const float* __restrict__ W1, const float* __restrict__ b1,
                      const float* __restrict__ W2, const float* __restrict__ b2) {
    __shared__ float fts[32 * LDA];   // ft tile  [32][64] (+pad)
    __shared__ float hs[32 * LDH];    // hidden chunk [32][256] (+pad), reused for output
    int tid = threadIdx.x;
    int wid = tid >> 5;
    int n0 = blockIdx.x * FNB;
    for (int idx = tid; idx < FNB * 64; idx += 256) {
        int j = idx >> 6, d = idx & 63;
        fts[j * LDA + d] = (n0 + j < N_NODES) ? g_ft[(n0 + j) * DM_ + d] : 0.0f;
    }
    __syncthreads();
    // preload A fragments for GEMM1 (ft): 2 m-tiles x 8 k-tiles
    wmma::fragment<wmma::matrix_a, 16, 16, 8, wmma::precision::tf32, wmma::row_major> aF[2][8];
#pragma unroll
    for (int mt = 0; mt < 2; mt++)
#pragma unroll
        for (int kt = 0; kt < 8; kt++) {
            wmma::load_matrix_sync(aF[mt][kt], fts + mt * 16 * LDA + kt * 8, LDA);
#pragma unroll
            for (int i = 0; i < aF[mt][kt].num_elements; i++)
                aF[mt][kt].x[i] = wmma::__float_to_tf32(aF[mt][kt].x[i]);
        }
    // GEMM2 accumulators: warp owns output cols [wid*32, wid*32+32) -> 2 n-tiles x 2 m-tiles
    wmma::fragment<wmma::accumulator, 16, 16, 8, float> d2[2][2];
#pragma unroll
    for (int mt = 0; mt < 2; mt++)
#pragma unroll
        for (int nt = 0; nt < 2; nt++) wmma::fill_fragment(d2[mt][nt], 0.0f);

    for (int ch = 0; ch < 4; ch++) {
        __syncthreads();   // hs free for new chunk
        // GEMM1 chunk: hidden cols [ch*256, ch*256+256); warp computes 2 n-tiles
#pragma unroll
        for (int nt = 0; nt < 2; nt++) {
            int hcol = ch * 256 + (wid * 2 + nt) * 16;
#pragma unroll
            for (int mt = 0; mt < 2; mt++) {
                wmma::fragment<wmma::accumulator, 16, 16, 8, float> cf;
                wmma::fill_fragment(cf, 0.0f);
#pragma unroll
                for (int kt = 0; kt < 8; kt++) {
                    wmma::fragment<wmma::matrix_b, 16, 16, 8, wmma::precision::tf32, wmma::row_major> bF;
                    wmma::load_matrix_sync(bF, W1 + (size_t)(kt * 8) * H_ + hcol, H_);
#pragma unroll
                    for (int i = 0; i < bF.num_elements; i++)
                        bF.x[i] = wmma::__float_to_tf32(bF.x[i]);
                    wmma::mma_sync(cf, aF[mt][kt], bF, cf);
                }
                wmma::store_matrix_sync(hs + mt * 16 * LDH + (wid * 2 + nt) * 16, cf, LDH,
                                        wmma::mem_row_major);
            }
        }
        __syncthreads();
        // bias + silu elementwise on the chunk
        for (int idx = tid; idx < 32 * 256; idx += 256) {
            int j = idx >> 8, hc = idx & 255;
            float v = hs[j * LDH + hc] + __ldg(b1 + ch * 256 + hc);
            hs[j * LDH + hc] = silu_f(v);
        }
        __syncthreads();
        // GEMM2 partial: A = hs [32][256] tf32, B = W2 rows [ch*256, +256)
        for (int kt = 0; kt < 32; kt++) {
            wmma::fragment<wmma::matrix_a, 16, 16, 8, wmma::precision::tf32, wmma::row_major> a2[2];
#pragma unroll
            for (int mt = 0; mt < 2; mt++) {
                wmma::load_matrix_sync(a2[mt], hs + mt * 16 * LDH + kt * 8, LDH);
#pragma unroll
                for (int i = 0; i < a2[mt].num_elements; i++)
                    a2[mt].x[i] = wmma::__float_to_tf32(a2[mt].x[i]);
            }
#pragma unroll
            for (int nt = 0; nt < 2; nt++) {
                wmma::fragment<wmma::matrix_b, 16, 16, 8, wmma::precision::tf32, wmma::row_major> b2F;
                wmma::load_matrix_sync(b2F, W2 + (size_t)(ch * 256 + kt * 8) * D_ + wid * 32 + nt * 16, D_);
#pragma unroll
                for (int i = 0; i < b2F.num_elements; i++)
                    b2F.x[i] = wmma::__float_to_tf32(b2F.x[i]);
#pragma unroll
                for (int mt = 0; mt < 2; mt++)
                    wmma::mma_sync(d2[mt][nt], a2[mt], b2F, d2[mt][nt]);
            }
        }
    }
    // epilogue: D -> smem -> bias -> gmem
    __syncthreads();
#pragma unroll
    for (int mt = 0; mt < 2; mt++)
#pragma unroll
        for (int nt = 0; nt < 2; nt++)
            wmma::store_matrix_sync(hs + mt * 16 * LDH + wid * 32 + nt * 16, d2[mt][nt], LDH,
                                    wmma::mem_row_major);
    __syncthreads();
    float* xo = g_x[nxt];
    for (int idx = tid; idx < 32 * 256; idx += 256) {
        int j = idx >> 8, col = idx & 255;
        if (n0 + j < N_NODES)
            xo[(n0 + j) * D_ + col] = hs[j * LDH + col] + __ldg(b2 + col);
    }
}

__global__ void k_zero(float* out) {
    if (blockIdx.x == 0 && threadIdx.x == 0) out[0] = 0.0f;
}

__global__ void k_fc(int cur, const float* __restrict__ Wfc, const float* __restrict__ bfc,
                     float* out) {
    __shared__ float wf[D_];
    __shared__ float red[8];
    for (int i = threadIdx.x; i < D_; i += 256) wf[i] = Wfc[i];
    __syncthreads();
    const float* x = g_x[cur];
    float local = 0.0f;
    int stride = gridDim.x * 256;
    for (int idx = blockIdx.x * 256 + threadIdx.x; idx < N_NODES * D_; idx += stride)
        local += x[idx] * wf[idx & 255];
#pragma unroll
    for (int off = 16; off; off >>= 1) local += __shfl_xor_sync(0xffffffffu, local, off);
    if ((threadIdx.x & 31) == 0) red[threadIdx.x >> 5] = local;
    __syncthreads();
    if (threadIdx.x < 8) {
        float v = red[threadIdx.x];
#pragma unroll
        for (int off = 4; off; off >>= 1) v += __shfl_xor_sync(0xffu, v, off);
        if (threadIdx.x == 0) atomicAdd(out, v * (1.0f / (float)N_NODES));
    }
    if (blockIdx.x == 0 && threadIdx.x == 0) atomicAdd(out, __ldg(bfc));
}

// ---------------- host ----------------
extern "C" void kernel_launch(void* const* d_in, const int* in_sizes, int n_in,
                              void* d_out, int out_size) {
    const int*   an    = (const int*)d_in[0];
    const int*   gs    = (const int*)d_in[1];
    const int*   gd    = (const int*)d_in[2];
    const int*   tsp   = (const int*)d_in[3];
    const int*   tdp   = (const int*)d_in[4];
    const float* r     = (const float*)d_in[5];
    const float* emb   = (const float*)d_in[6];
    const float* Wsrc  = (const float*)d_in[7];
    const float* bsrc  = (const float*)d_in[8];
    const float* Wdst  = (const float*)d_in[9];
    const float* bdst  = (const float*)d_in[10];
    const float* Wedge = (const float*)d_in[11];
    const float* bedge = (const float*)d_in[12];
    const float* attn  = (const float*)d_in[13];
    const float* W1    = (const float*)d_in[14];
    const float* b1    = (const float*)d_in[15];
    const float* W2    = (const float*)d_in[16];
    const float* b2    = (const float*)d_in[17];
    const float* Wfc   = (const float*)d_in[18];
    const float* bfc   = (const float*)d_in[19];
    float* out = (float*)d_out;

    const int scan_blocks = (N_EDGES + 1 + 2047) / 2048;   // 79

    k_setup<<<(N_NODES * D_ + 255) / 256, 256>>>(an, emb, r);
    k_hist<<<(N_TRIP + 255) / 256, 256>>>(tdp);
    k_scanA<<<scan_blocks, 256>>>();
    k_scanB<<<1, 128>>>(scan_blocks);
    k_scanC<<<(N_EDGES + 256) / 256, 256>>>();
    k_scatter<<<(N_TRIP + 255) / 256, 256>>>(tsp, tdp);

    int cur = 0;
    for (int l = 0; l < L_; l++) {
        k_nodeproj<<<N_NODES / 8, 128>>>(cur, Wsrc + l * D_ * DM_, bsrc + l * DM_,
                                         Wdst + l * D_ * DM_, bdst + l * DM_);
        k_exij<<<N_EDGES / 4, 256>>>(gs, gd, Wedge + l * D_ * DM_, bedge + l * DM_);
        k_initft<<<(N_NODES * DM_ + 255) / 256, 256>>>();
        k_trip<<<N_EDGES / 16, 256>>>(gd, attn + l * DM_);
        k_ffn<<<(N_NODES + FNB - 1) / FNB, 256>>>(1 - cur, W1 + l * DM_ * H_, b1 + l * H_,
                                                  W2 + l * H_ * D_, b2 + l * D_);
        cur = 1 - cur;
    }
    k_zero<<<1, 1>>>(out);
    k_fc<<<256, 256>>>(cur, Wfc, bfc, out);
}